// round 13
// baseline (speedup 1.0000x reference)
#include <cuda_runtime.h>
#include <cuda_bf16.h>
#include <math.h>
#include <stdint.h>

#define NHH 8
#define ED 256
#define SQL 1024
#define BSZ 4
#define QKV (NHH*3*ED)   /* 6144 */
#define NE  (NHH*ED)     /* 2048 */
#define TOK (BSZ*SQL)    /* 4096 */
#define NBH (BSZ*NHH)    /* 32 */

// ---------------------------------------------------------------------------
// Device-global scratch. hi/lo split-bf16: packed u32 = (elem2i, elem2i+1).
// ---------------------------------------------------------------------------
__device__ unsigned g_xh [(size_t)TOK*ED/2],  g_xl [(size_t)TOK*ED/2];
__device__ unsigned g_wah[(size_t)QKV*ED/2],  g_wal[(size_t)QKV*ED/2];
__device__ unsigned g_woh[(size_t)ED*NE/2],   g_wol[(size_t)ED*NE/2];
__device__ unsigned g_qh [(size_t)NBH*SQL*ED/2], g_ql [(size_t)NBH*SQL*ED/2];
__device__ unsigned g_kh [(size_t)NBH*SQL*ED/2], g_kl [(size_t)NBH*SQL*ED/2];
__device__ unsigned g_vh [(size_t)NBH*SQL*ED/2], g_vl [(size_t)NBH*SQL*ED/2];
__device__ unsigned g_ah [(size_t)TOK*NE/2],  g_al [(size_t)TOK*NE/2];
__device__ float    g_scores[(size_t)NBH*SQL*SQL];
__device__ float    g_op0[(size_t)TOK*ED], g_op1[(size_t)TOK*ED];

#define BM 128
#define BN 64
#define BK 16
#define STRIDE 12
#define STG_B 18432u   /* NT stage: A hi/lo 2x6144 + B hi/lo 2x3072 */
#define BPITCH 144u    /* V tile row pitch (128 B data + 16 pad) */
#define STG_F 14848u   /* fused stage: S 128x80B + V hi/lo 2x2304 */
#define NPIPE 4
#define SMEM_SZ (NPIPE*18432)

__device__ __forceinline__ unsigned smem_u32(const void* p) {
    unsigned a;
    asm("{ .reg .u64 t; cvta.to.shared.u64 t, %1; cvt.u32.u64 %0, t; }" : "=r"(a) : "l"(p));
    return a;
}

__device__ __forceinline__ void split2(float a, float b, unsigned &h, unsigned &l) {
    __nv_bfloat16 ah = __float2bfloat16(a), bh = __float2bfloat16(b);
    float ar = a - __bfloat162float(ah);
    float br = b - __bfloat162float(bh);
    __nv_bfloat16 al = __float2bfloat16(ar), bl = __float2bfloat16(br);
    h = (unsigned)__bfloat16_as_ushort(ah) | ((unsigned)__bfloat16_as_ushort(bh) << 16);
    l = (unsigned)__bfloat16_as_ushort(al) | ((unsigned)__bfloat16_as_ushort(bl) << 16);
}

#define MMA_BF16(C, A0, A1, A2, A3, B0, B1)                                      \
    asm volatile("mma.sync.aligned.m16n8k16.row.col.f32.bf16.bf16.f32 "          \
        "{%0,%1,%2,%3}, {%4,%5,%6,%7}, {%8,%9}, {%0,%1,%2,%3};"                  \
        : "+f"((C)[0]), "+f"((C)[1]), "+f"((C)[2]), "+f"((C)[3])                  \
        : "r"(A0), "r"(A1), "r"(A2), "r"(A3), "r"(B0), "r"(B1))

__device__ __forceinline__ void ldsm4(unsigned addr, unsigned r[4]) {
    asm volatile("ldmatrix.sync.aligned.m8n8.x4.shared.b16 {%0,%1,%2,%3}, [%4];"
        : "=r"(r[0]), "=r"(r[1]), "=r"(r[2]), "=r"(r[3]) : "r"(addr));
}
__device__ __forceinline__ void ldsm4t(unsigned addr, unsigned r[4]) {
    asm volatile("ldmatrix.sync.aligned.m8n8.x4.trans.shared.b16 {%0,%1,%2,%3}, [%4];"
        : "=r"(r[0]), "=r"(r[1]), "=r"(r[2]), "=r"(r[3]) : "r"(addr));
}

// NT stage: 8 warps 4m x 2n; warp tile 32x32; 3 MMAs per tile (split-bf16).
__device__ __forceinline__ void compute_stage(
    unsigned Ah, unsigned Al, unsigned Bh, unsigned Bl,
    int wm, int wn, int lane, float acc[2][4][4])
{
    const int lrow = (lane & 7) | (((lane >> 3) & 1) << 3);
    const int lcw  = (lane >> 4) * 4;
    const unsigned aoff = (unsigned)(((wm*32 + lrow) * STRIDE + lcw) * 4);
    const unsigned boff = (unsigned)(((wn*32 + lrow) * STRIDE + lcw) * 4);

    unsigned ah[2][4], al[2][4];
    #pragma unroll
    for (int mt = 0; mt < 2; mt++) {
        ldsm4(Ah + aoff + (unsigned)(mt*16*STRIDE*4), ah[mt]);
        ldsm4(Al + aoff + (unsigned)(mt*16*STRIDE*4), al[mt]);
    }
    #pragma unroll
    for (int ntp = 0; ntp < 2; ntp++) {
        unsigned bh[4], bl[4];
        ldsm4(Bh + boff + (unsigned)(ntp*16*STRIDE*4), bh);
        ldsm4(Bl + boff + (unsigned)(ntp*16*STRIDE*4), bl);
        #pragma unroll
        for (int sub = 0; sub < 2; sub++) {
            const int nt = ntp*2 + sub;
            #pragma unroll
            for (int mt = 0; mt < 2; mt++) {
                MMA_BF16(acc[mt][nt], ah[mt][0], ah[mt][1], ah[mt][2], ah[mt][3], bh[sub], bh[2+sub]);
                MMA_BF16(acc[mt][nt], ah[mt][0], ah[mt][1], ah[mt][2], ah[mt][3], bl[sub], bl[2+sub]);
                MMA_BF16(acc[mt][nt], al[mt][0], al[mt][1], al[mt][2], al[mt][3], bh[sub], bh[2+sub]);
            }
        }
    }
}

#define CPA(dst, src) \
    asm volatile("cp.async.cg.shared.global [%0], [%1], 16;" :: "r"(dst), "l"(src))

#define ISSUE_STAGE(s, b) {                                                       \
    unsigned d_ = smb + (unsigned)(b)*STG_B + (unsigned)(lr*48 + half*16);        \
    CPA(d_,         aH + (size_t)(s)*8);                                          \
    CPA(d_ + 6144u, aL + (size_t)(s)*8);                                          \
    if (t < 128) {                                                                \
        unsigned e_ = smb + (unsigned)(b)*STG_B + 12288u + (unsigned)(lr*48 + half*16); \
        CPA(e_,         bH + (size_t)(s)*8);                                      \
        CPA(e_ + 3072u, bL + (size_t)(s)*8);                                      \
    }                                                                             \
    asm volatile("cp.async.commit_group;" ::: "memory"); }

#define GEMM_LOOP(NS_) {                                                          \
    ISSUE_STAGE(0, 0);                                                            \
    ISSUE_STAGE(1, 1);                                                            \
    ISSUE_STAGE(2, 2);                                                            \
    for (int i = 0; i < (NS_); i++) {                                             \
        const int rem = (NS_) - 1 - i;                                            \
        if (rem >= 2)      { asm volatile("cp.async.wait_group 2;" ::: "memory"); }\
        else if (rem == 1) { asm volatile("cp.async.wait_group 1;" ::: "memory"); }\
        else               { asm volatile("cp.async.wait_group 0;" ::: "memory"); }\
        __syncthreads();                                                          \
        const unsigned bb = smb + (unsigned)(i & 3) * STG_B;                      \
        compute_stage(bb, bb + 6144u, bb + 12288u, bb + 15360u, wm, wn, lane, acc);\
        if (i + 3 < (NS_)) ISSUE_STAGE(i + 3, (i + 3) & 3);                       \
    } }

// ---------------------------------------------------------------------------
// Fused softmax+PV chunk: raw S fp32 from smem -> causal mask -> online
// softmax (running m/l, acc rescale) -> split-bf16 A-frags in registers ->
// 3-MMA PV against V (trans ldsm).
// ---------------------------------------------------------------------------
__device__ __forceinline__ void fused_chunk(
    const char* sm, unsigned smbs, int i, int q0,
    int wm, int wn, int lane,
    float acc[2][4][4], float mS[2][2], float lS[2][2])
{
    const int g = lane >> 2, qq = lane & 3;
    const int kbase = i * 16;
    unsigned pha[2][4], pla[2][4];

    #pragma unroll
    for (int mt = 0; mt < 2; mt++) {
        const int r0 = wm*32 + mt*16 + g;
        const int qr0 = q0 + r0, qr1 = qr0 + 8;
        float2 f0 = *(const float2*)(sm + r0*80 + qq*8);
        float2 f1 = *(const float2*)(sm + (r0+8)*80 + qq*8);
        float2 f2 = *(const float2*)(sm + r0*80 + 32 + qq*8);
        float2 f3 = *(const float2*)(sm + (r0+8)*80 + 32 + qq*8);
        const int c0 = kbase + 2*qq, c2 = c0 + 8;
        float s00 = (c0   <= qr0) ? f0.x : -1e30f;
        float s01 = (c0+1 <= qr0) ? f0.y : -1e30f;
        float s10 = (c0   <= qr1) ? f1.x : -1e30f;
        float s11 = (c0+1 <= qr1) ? f1.y : -1e30f;
        float s02 = (c2   <= qr0) ? f2.x : -1e30f;
        float s03 = (c2+1 <= qr0) ? f2.y : -1e30f;
        float s12 = (c2   <= qr1) ? f3.x : -1e30f;
        float s13 = (c2+1 <= qr1) ? f3.y : -1e30f;

        float mr0 = fmaxf(fmaxf(s00, s01), fmaxf(s02, s03));
        float mr1 = fmaxf(fmaxf(s10, s11), fmaxf(s12, s13));
        mr0 = fmaxf(mr0, __shfl_xor_sync(0xffffffffu, mr0, 1));
        mr0 = fmaxf(mr0, __shfl_xor_sync(0xffffffffu, mr0, 2));
        mr1 = fmaxf(mr1, __shfl_xor_sync(0xffffffffu, mr1, 1));
        mr1 = fmaxf(mr1, __shfl_xor_sync(0xffffffffu, mr1, 2));

        float mn0 = fmaxf(mS[mt][0], mr0), mn1 = fmaxf(mS[mt][1], mr1);
        float sf0 = __expf(mS[mt][0] - mn0), sf1 = __expf(mS[mt][1] - mn1);
        mS[mt][0] = mn0; mS[mt][1] = mn1;

        float p00 = __expf(s00 - mn0), p01 = __expf(s01 - mn0);
        float p02 = __expf(s02 - mn0), p03 = __expf(s03 - mn0);
        float p10 = __expf(s10 - mn1), p11 = __expf(s11 - mn1);
        float p12 = __expf(s12 - mn1), p13 = __expf(s13 - mn1);

        float su0 = p00 + p01 + p02 + p03;
        float su1 = p10 + p11 + p12 + p13;
        su0 += __shfl_xor_sync(0xffffffffu, su0, 1);
        su0 += __shfl_xor_sync(0xffffffffu, su0, 2);
        su1 += __shfl_xor_sync(0xffffffffu, su1, 1);
        su1 += __shfl_xor_sync(0xffffffffu, su1, 2);
        lS[mt][0] = lS[mt][0]*sf0 + su0;
        lS[mt][1] = lS[mt][1]*sf1 + su1;

        #pragma unroll
        for (int nt = 0; nt < 4; nt++) {
            acc[mt][nt][0] *= sf0; acc[mt][nt][1] *= sf0;
            acc[mt][nt][2] *= sf1; acc[mt][nt][3] *= sf1;
        }
        split2(p00, p01, pha[mt][0], pla[mt][0]);  // a0: row g,   k lo
        split2(p10, p11, pha[mt][1], pla[mt][1]);  // a1: row g+8, k lo
        split2(p02, p03, pha[mt][2], pla[mt][2]);  // a2: row g,   k hi
        split2(p12, p13, pha[mt][3], pla[mt][3]);  // a3: row g+8, k hi
    }

    // PV MMAs: V b-frags via trans ldsm (V tile 16k x 64d, pitch 144B)
    const int bk  = ((lane >> 4) & 1) * 8 + (lane & 7);
    const int bnh = (lane >> 3) & 1;
    const unsigned boff = (unsigned)(bk * BPITCH + (unsigned)(wn*64 + bnh*16));
    const unsigned Bh = smbs + 10240u, Bl = smbs + 12544u;
    #pragma unroll
    for (int ntp = 0; ntp < 2; ntp++) {
        unsigned bh[4], bl[4];
        ldsm4t(Bh + boff + (unsigned)(ntp*32), bh);
        ldsm4t(Bl + boff + (unsigned)(ntp*32), bl);
        #pragma unroll
        for (int sub = 0; sub < 2; sub++) {
            const int nt = ntp*2 + sub;
            #pragma unroll
            for (int mt = 0; mt < 2; mt++) {
                MMA_BF16(acc[mt][nt], pha[mt][0], pha[mt][1], pha[mt][2], pha[mt][3], bh[sub], bh[2+sub]);
                MMA_BF16(acc[mt][nt], pha[mt][0], pha[mt][1], pha[mt][2], pha[mt][3], bl[sub], bl[2+sub]);
                MMA_BF16(acc[mt][nt], pla[mt][0], pla[mt][1], pla[mt][2], pla[mt][3], bh[sub], bh[2+sub]);
            }
        }
    }
}

// ---------------------------------------------------------------------------
// Kernel 0: pre-split all three fp32 operands -> hi/lo packed bf16
// ---------------------------------------------------------------------------
#define NXW  (TOK*ED/2)
#define NWAW (QKV*ED/2)
#define NWOW (ED*NE/2)
__global__ void __launch_bounds__(256) split_all(const float* __restrict__ x,
                                                 const float* __restrict__ wa,
                                                 const float* __restrict__ wo) {
    int i = blockIdx.x * 256 + threadIdx.x;
    const float* src; unsigned *H, *L; int j = i;
    if (j < NXW)              { src = x;  H = g_xh;  L = g_xl; }
    else if ((j -= NXW) < NWAW) { src = wa; H = g_wah; L = g_wal; }
    else if ((j -= NWAW) < NWOW){ src = wo; H = g_woh; L = g_wol; }
    else return;
    float2 v = ((const float2*)src)[j];
    unsigned h, l;
    split2(v.x, v.y, h, l);
    H[j] = h; L[j] = l;
}

// Q/K/V epilogue writer: raw-view remap baked in. row = global token, col in [0,2048)
__device__ __forceinline__ void write_qk(unsigned* H, unsigned* L, int row, int col,
                                         float v0, float v1) {
    int b = row >> 10, sp = row & 1023;
    int h = sp >> 7, s = ((sp & 127) << 3) + (col >> 8), d = col & 255;
    size_t idx = ((((size_t)(b*8 + h)) * SQL + s) << 7) + (d >> 1);
    unsigned hh, ll;
    split2(v0, v1, hh, ll);
    H[idx] = hh; L[idx] = ll;
}

// ---------------------------------------------------------------------------
// Kernel 1: proj = x @ w_attn^T + b_attn; scatters Q,K,V split-bf16
// ---------------------------------------------------------------------------
__global__ void __launch_bounds__(256, 3) proj_gemm(const float* __restrict__ bias) {
    extern __shared__ unsigned smd[];
    const unsigned smb = smem_u32(smd);
    const int m0 = blockIdx.y * BM, n0 = blockIdx.x * BN;
    const int t = threadIdx.x, lane = t & 31, w = t >> 5;
    const int wm = w >> 1, wn = w & 1;
    const int lr = t >> 1, half = t & 1;
    const unsigned* aH = g_xh  + (size_t)(m0 + lr) * 128 + half*4;
    const unsigned* aL = g_xl  + (size_t)(m0 + lr) * 128 + half*4;
    const unsigned* bH = g_wah + (size_t)(n0 + lr) * 128 + half*4;
    const unsigned* bL = g_wal + (size_t)(n0 + lr) * 128 + half*4;
    float acc[2][4][4] = {};
    GEMM_LOOP(ED/BK);

    const int g = lane >> 2, qq = lane & 3;
    #pragma unroll
    for (int mt = 0; mt < 2; mt++) {
        int row = m0 + wm*32 + mt*16 + g;
        #pragma unroll
        for (int nt = 0; nt < 4; nt++) {
            int col = n0 + wn*32 + nt*8 + qq*2;
            float bv0 = bias[col], bv1 = bias[col+1];
            float p0 = acc[mt][nt][0] + bv0, p1 = acc[mt][nt][1] + bv1;
            float p2 = acc[mt][nt][2] + bv0, p3 = acc[mt][nt][3] + bv1;
            unsigned *H, *L; int c;
            if (col < NE)          { H = g_qh; L = g_ql; c = col; }
            else if (col < 2*NE)   { H = g_kh; L = g_kl; c = col - NE; }
            else                   { H = g_vh; L = g_vl; c = col - 2*NE; }
            write_qk(H, L, row,   c, p0, p1);
            write_qk(H, L, row+8, c, p2, p3);
        }
    }
}

// ---------------------------------------------------------------------------
// Kernel 2: scores = (Q·K^T)/16; skip tiles fully above diagonal
// ---------------------------------------------------------------------------
__global__ void __launch_bounds__(256, 3) score_gemm() {
    const int q0 = blockIdx.y * BM, k0 = blockIdx.x * BN;
    if (k0 > q0 + (BM - 1)) return;
    const int bh = blockIdx.z;
    extern __shared__ unsigned smd[];
    const unsigned smb = smem_u32(smd);
    const int t = threadIdx.x, lane = t & 31, w = t >> 5;
    const int wm = w >> 1, wn = w & 1;
    const int lr = t >> 1, half = t & 1;
    const unsigned* aH = g_qh + ((size_t)bh * SQL + q0 + lr) * 128 + half*4;
    const unsigned* aL = g_ql + ((size_t)bh * SQL + q0 + lr) * 128 + half*4;
    const unsigned* bH = g_kh + ((size_t)bh * SQL + k0 + lr) * 128 + half*4;
    const unsigned* bL = g_kl + ((size_t)bh * SQL + k0 + lr) * 128 + half*4;
    float acc[2][4][4] = {};
    GEMM_LOOP(ED/BK);

    float* S = g_scores + (size_t)bh * SQL * SQL;
    const int g = lane >> 2, qq = lane & 3;
    #pragma unroll
    for (int mt = 0; mt < 2; mt++) {
        int row = q0 + wm*32 + mt*16 + g;
        #pragma unroll
        for (int nt = 0; nt < 4; nt++) {
            int col = k0 + wn*32 + nt*8 + qq*2;
            float* d0 = S + (size_t)row * SQL + col;
            float* d1 = S + (size_t)(row+8) * SQL + col;
            *(float2*)d0 = make_float2(acc[mt][nt][0]*0.0625f, acc[mt][nt][1]*0.0625f);
            *(float2*)d1 = make_float2(acc[mt][nt][2]*0.0625f, acc[mt][nt][3]*0.0625f);
        }
    }
}

// ---------------------------------------------------------------------------
// Kernel 3 (fused): O = softmax_causal(S) @ V, online softmax in registers.
// ---------------------------------------------------------------------------
__global__ void __launch_bounds__(256, 2) pv_fused() {
    const int bh = blockIdx.z;
    const int q0 = (int)(gridDim.y - 1 - blockIdx.y) * BM;   // heavy tiles first
    const int n0 = blockIdx.x * BN;
    extern __shared__ unsigned smd[];
    const unsigned smb = smem_u32(smd);
    char* smx = (char*)smd;
    const int t = threadIdx.x, lane = t & 31, w = t >> 5;
    const int wm = w >> 1, wn = w & 1;
    const int NS = (q0 + BM) / BK;

    const float* sA = g_scores + ((size_t)bh * SQL + q0 + (t>>1)) * SQL + (t&1)*8;
    const unsigned* vbh = g_vh + ((size_t)bh * SQL + (t>>3)) * 128 + (n0>>1) + (t&7)*4;
    const unsigned* vbl = g_vl + ((size_t)bh * SQL + (t>>3)) * 128 + (n0>>1) + (t&7)*4;

    float acc[2][4][4] = {};
    float mS[2][2] = {{-1e30f,-1e30f},{-1e30f,-1e30f}};
    float lS[2][2] = {};

#define ISSUE_F(s, b) {                                                           \
    unsigned d_ = smb + (unsigned)(b)*STG_F + (unsigned)((t>>1)*80 + (t&1)*32);   \
    CPA(d_,       sA + (size_t)(s)*16);                                           \
    CPA(d_ + 16u, sA + (size_t)(s)*16 + 4);                                       \
    if (t < 128) {                                                                \
        unsigned e_ = smb + (unsigned)(b)*STG_F + 10240u                          \
                    + (unsigned)((t>>3)*BPITCH + (t&7)*16);                       \
        CPA(e_,         vbh + (size_t)(s)*16*128);                                \
        CPA(e_ + 2304u, vbl + (size_t)(s)*16*128);                                \
    }                                                                             \
    asm volatile("cp.async.commit_group;" ::: "memory"); }

    ISSUE_F(0, 0);
    ISSUE_F(1, 1);
    ISSUE_F(2, 2);
    for (int i = 0; i < NS; i++) {
        const int rem = NS - 1 - i;
        if (rem >= 2)      { asm volatile("cp.async.wait_group 2;" ::: "memory"); }
        else if (rem == 1) { asm volatile("cp.async.wait_group 1;" ::: "memory"); }
        else               { asm volatile("cp.async.wait_group 0;" ::: "memory"); }
        __syncthreads();
        fused_chunk(smx + (size_t)(i & 3) * STG_F, smb + (unsigned)(i & 3) * STG_F,
                    i, q0, wm, wn, lane, acc, mS, lS);
        if (i + 3 < NS) ISSUE_F(i + 3, (i + 3) & 3);
    }

    const int g = lane >> 2, qq = lane & 3;
    #pragma unroll
    for (int mt = 0; mt < 2; mt++) {
        const float inv0 = 1.f / lS[mt][0], inv1 = 1.f / lS[mt][1];
        int row = q0 + wm*32 + mt*16 + g;
        #pragma unroll
        for (int nt = 0; nt < 4; nt++) {
            int col = n0 + wn*32 + nt*8 + qq*2;
            size_t i0 = ((size_t)bh * SQL + row) * 128 + (col >> 1);
            size_t i1 = ((size_t)bh * SQL + row + 8) * 128 + (col >> 1);
            unsigned hh, ll;
            split2(acc[mt][nt][0]*inv0, acc[mt][nt][1]*inv0, hh, ll);
            g_ah[i0] = hh; g_al[i0] = ll;
            split2(acc[mt][nt][2]*inv1, acc[mt][nt][3]*inv1, hh, ll);
            g_ah[i1] = hh; g_al[i1] = ll;
        }
    }
}

// ---------------------------------------------------------------------------
// Kernel 4: out partials (split-K=2)
// ---------------------------------------------------------------------------
__global__ void __launch_bounds__(256, 3) out_gemm() {
    extern __shared__ unsigned smd[];
    const unsigned smb = smem_u32(smd);
    const int m0 = blockIdx.y * BM, n0 = blockIdx.x * BN;
    const int z = blockIdx.z;
    float* P = z ? g_op1 : g_op0;
    const int t = threadIdx.x, lane = t & 31, w = t >> 5;
    const int wm = w >> 1, wn = w & 1;
    const int lr = t >> 1, half = t & 1;
    const unsigned* aH = g_ah  + (size_t)(m0 + lr) * 1024 + z*512 + half*4;
    const unsigned* aL = g_al  + (size_t)(m0 + lr) * 1024 + z*512 + half*4;
    const unsigned* bH = g_woh + (size_t)(n0 + lr) * 1024 + z*512 + half*4;
    const unsigned* bL = g_wol + (size_t)(n0 + lr) * 1024 + z*512 + half*4;
    float acc[2][4][4] = {};
    GEMM_LOOP(NE/BK/2);

    const int g = lane >> 2, qq = lane & 3;
    #pragma unroll
    for (int mt = 0; mt < 2; mt++) {
        int row = m0 + wm*32 + mt*16 + g;
        #pragma unroll
        for (int nt = 0; nt < 4; nt++) {
            int col = n0 + wn*32 + nt*8 + qq*2;
            *(float2*)(P + (size_t)row * ED + col) =
                make_float2(acc[mt][nt][0], acc[mt][nt][1]);
            *(float2*)(P + (size_t)(row+8) * ED + col) =
                make_float2(acc[mt][nt][2], acc[mt][nt][3]);
        }
    }
}

// Kernel 5: C = op0 + op1 + bias
__global__ void __launch_bounds__(256) out_reduce(const float* __restrict__ bias,
                                                  float* __restrict__ C) {
    int i = blockIdx.x * 256 + threadIdx.x;
    float4 a = ((const float4*)g_op0)[i];
    float4 b = ((const float4*)g_op1)[i];
    int col = (i * 4) & (ED - 1);
    float4 bb = *(const float4*)(bias + col);
    ((float4*)C)[i] = make_float4(a.x+b.x+bb.x, a.y+b.y+bb.y, a.z+b.z+bb.z, a.w+b.w+bb.w);
}

extern "C" void kernel_launch(void* const* d_in, const int* in_sizes, int n_in,
                              void* d_out, int out_size) {
    const float* x      = (const float*)d_in[0];
    const float* w_attn = (const float*)d_in[1];
    const float* b_attn = (const float*)d_in[2];
    const float* w_out  = (const float*)d_in[3];
    const float* b_out  = (const float*)d_in[4];
    float* out = (float*)d_out;

    cudaFuncSetAttribute(proj_gemm,  cudaFuncAttributeMaxDynamicSharedMemorySize, SMEM_SZ);
    cudaFuncSetAttribute(score_gemm, cudaFuncAttributeMaxDynamicSharedMemorySize, SMEM_SZ);
    cudaFuncSetAttribute(pv_fused,   cudaFuncAttributeMaxDynamicSharedMemorySize, NPIPE*STG_F);
    cudaFuncSetAttribute(out_gemm,   cudaFuncAttributeMaxDynamicSharedMemorySize, SMEM_SZ);

    const int NTOT = NXW + NWAW + NWOW;
    split_all<<<(NTOT + 255)/256, 256>>>(x, w_attn, w_out);

    proj_gemm<<<dim3(QKV/BN, TOK/BM), 256, SMEM_SZ>>>(b_attn);
    score_gemm<<<dim3(SQL/BN, SQL/BM, NBH), 256, SMEM_SZ>>>();
    pv_fused<<<dim3(ED/BN, SQL/BM, NBH), 256, NPIPE*STG_F>>>();
    out_gemm<<<dim3(ED/BN, TOK/BM, 2), 256, SMEM_SZ>>>();
    out_reduce<<<TOK*ED/4/256, 256>>>(b_out, out);
}

// round 14
// speedup vs baseline: 1.1651x; 1.1651x over previous
#include <cuda_runtime.h>
#include <cuda_bf16.h>
#include <math.h>
#include <stdint.h>

#define NHH 8
#define ED 256
#define SQL 1024
#define BSZ 4
#define QKV (NHH*3*ED)   /* 6144 */
#define NE  (NHH*ED)     /* 2048 */
#define TOK (BSZ*SQL)    /* 4096 */
#define NBH (BSZ*NHH)    /* 32 */

// ---------------------------------------------------------------------------
// Device-global scratch. hi/lo split-bf16: packed u32 = (elem2i, elem2i+1).
// Q, K, V all stored natural [bh][s][d/2] (raw-view remap applied at write).
// ---------------------------------------------------------------------------
__device__ unsigned g_xh [(size_t)TOK*ED/2],  g_xl [(size_t)TOK*ED/2];
__device__ unsigned g_wah[(size_t)QKV*ED/2],  g_wal[(size_t)QKV*ED/2];
__device__ unsigned g_woh[(size_t)ED*NE/2],   g_wol[(size_t)ED*NE/2];
__device__ unsigned g_qh [(size_t)NBH*SQL*ED/2], g_ql [(size_t)NBH*SQL*ED/2];
__device__ unsigned g_kh [(size_t)NBH*SQL*ED/2], g_kl [(size_t)NBH*SQL*ED/2];
__device__ unsigned g_vh [(size_t)NBH*SQL*ED/2], g_vl [(size_t)NBH*SQL*ED/2];
__device__ unsigned g_ph [(size_t)NBH*SQL*SQL/2], g_pl [(size_t)NBH*SQL*SQL/2];
__device__ unsigned g_ah [(size_t)TOK*NE/2],  g_al [(size_t)TOK*NE/2];
__device__ float    g_scores[(size_t)NBH*SQL*SQL];
__device__ float    g_op0[(size_t)TOK*ED], g_op1[(size_t)TOK*ED], g_op2[(size_t)TOK*ED];

#define BM 128
#define BN 64          /* block tile 128x64; warp tile 32x32 */
#define BK 16
#define STRIDE 12      /* A/B(NT) smem rows: 8 used u32 + 4 pad */
#define STG_B 18432u   /* NT stage: A hi/lo 2x6144 + B hi/lo 2x3072 */
#define BPITCH 144u    /* pv B tile row pitch (128 B data + 16 pad) */
#define STG_PV 16896u  /* pv stage: A hi/lo 2x6144 + B hi/lo 2x2304 */
#define NPIPE 4
#define SMEM_SZ (NPIPE*18432)   /* 72 KB per CTA -> 3 CTAs/SM */

__device__ __forceinline__ unsigned smem_u32(const void* p) {
    unsigned a;
    asm("{ .reg .u64 t; cvta.to.shared.u64 t, %1; cvt.u32.u64 %0, t; }" : "=r"(a) : "l"(p));
    return a;
}

__device__ __forceinline__ void split2(float a, float b, unsigned &h, unsigned &l) {
    __nv_bfloat16 ah = __float2bfloat16(a), bh = __float2bfloat16(b);
    float ar = a - __bfloat162float(ah);
    float br = b - __bfloat162float(bh);
    __nv_bfloat16 al = __float2bfloat16(ar), bl = __float2bfloat16(br);
    h = (unsigned)__bfloat16_as_ushort(ah) | ((unsigned)__bfloat16_as_ushort(bh) << 16);
    l = (unsigned)__bfloat16_as_ushort(al) | ((unsigned)__bfloat16_as_ushort(bl) << 16);
}

#define MMA_BF16(C, A0, A1, A2, A3, B0, B1)                                      \
    asm volatile("mma.sync.aligned.m16n8k16.row.col.f32.bf16.bf16.f32 "          \
        "{%0,%1,%2,%3}, {%4,%5,%6,%7}, {%8,%9}, {%0,%1,%2,%3};"                  \
        : "+f"((C)[0]), "+f"((C)[1]), "+f"((C)[2]), "+f"((C)[3])                  \
        : "r"(A0), "r"(A1), "r"(A2), "r"(A3), "r"(B0), "r"(B1))

__device__ __forceinline__ void ldsm4(unsigned addr, unsigned r[4]) {
    asm volatile("ldmatrix.sync.aligned.m8n8.x4.shared.b16 {%0,%1,%2,%3}, [%4];"
        : "=r"(r[0]), "=r"(r[1]), "=r"(r[2]), "=r"(r[3]) : "r"(addr));
}
__device__ __forceinline__ void ldsm4t(unsigned addr, unsigned r[4]) {
    asm volatile("ldmatrix.sync.aligned.m8n8.x4.trans.shared.b16 {%0,%1,%2,%3}, [%4];"
        : "=r"(r[0]), "=r"(r[1]), "=r"(r[2]), "=r"(r[3]) : "r"(addr));
}

// NT stage: B tile rows = n (8 u32 along k), non-trans ldsm. Warp tile 32x32.
__device__ __forceinline__ void compute_stage(
    unsigned Ah, unsigned Al, unsigned Bh, unsigned Bl,
    int wm, int wn, int lane, float acc[2][4][4])
{
    const int lrow = (lane & 7) | (((lane >> 3) & 1) << 3);
    const int lcw  = (lane >> 4) * 4;
    const unsigned aoff = (unsigned)(((wm*32 + lrow) * STRIDE + lcw) * 4);
    const unsigned boff = (unsigned)(((wn*32 + lrow) * STRIDE + lcw) * 4);

    unsigned ah[2][4], al[2][4];
    #pragma unroll
    for (int mt = 0; mt < 2; mt++) {
        ldsm4(Ah + aoff + (unsigned)(mt*16*STRIDE*4), ah[mt]);
        ldsm4(Al + aoff + (unsigned)(mt*16*STRIDE*4), al[mt]);
    }
    #pragma unroll
    for (int ntp = 0; ntp < 2; ntp++) {
        unsigned bh[4], bl[4];
        ldsm4(Bh + boff + (unsigned)(ntp*16*STRIDE*4), bh);
        ldsm4(Bl + boff + (unsigned)(ntp*16*STRIDE*4), bl);
        #pragma unroll
        for (int sub = 0; sub < 2; sub++) {
            const int nt = ntp*2 + sub;
            #pragma unroll
            for (int mt = 0; mt < 2; mt++) {
                MMA_BF16(acc[mt][nt], ah[mt][0], ah[mt][1], ah[mt][2], ah[mt][3], bh[sub], bh[2+sub]);
                MMA_BF16(acc[mt][nt], ah[mt][0], ah[mt][1], ah[mt][2], ah[mt][3], bl[sub], bl[2+sub]);
                MMA_BF16(acc[mt][nt], al[mt][0], al[mt][1], al[mt][2], al[mt][3], bh[sub], bh[2+sub]);
            }
        }
    }
}

// PV stage: B tile rows = k (16 rows x 128B bf16 along n=d, pitch 144B), trans ldsm.
__device__ __forceinline__ void compute_stage_pv(
    unsigned Ah, unsigned Al, unsigned Bh, unsigned Bl,
    int wm, int wn, int lane, float acc[2][4][4])
{
    const int lrow = (lane & 7) | (((lane >> 3) & 1) << 3);
    const int lcw  = (lane >> 4) * 4;
    const unsigned aoff = (unsigned)(((wm*32 + lrow) * STRIDE + lcw) * 4);
    const int bk  = ((lane >> 4) & 1) * 8 + (lane & 7);
    const int bnh = (lane >> 3) & 1;
    const unsigned boff = (unsigned)(bk * BPITCH + (unsigned)(wn*64 + bnh*16));

    unsigned ah[2][4], al[2][4];
    #pragma unroll
    for (int mt = 0; mt < 2; mt++) {
        ldsm4(Ah + aoff + (unsigned)(mt*16*STRIDE*4), ah[mt]);
        ldsm4(Al + aoff + (unsigned)(mt*16*STRIDE*4), al[mt]);
    }
    #pragma unroll
    for (int ntp = 0; ntp < 2; ntp++) {
        unsigned bh[4], bl[4];
        ldsm4t(Bh + boff + (unsigned)(ntp*32), bh);
        ldsm4t(Bl + boff + (unsigned)(ntp*32), bl);
        #pragma unroll
        for (int sub = 0; sub < 2; sub++) {
            const int nt = ntp*2 + sub;
            #pragma unroll
            for (int mt = 0; mt < 2; mt++) {
                MMA_BF16(acc[mt][nt], ah[mt][0], ah[mt][1], ah[mt][2], ah[mt][3], bh[sub], bh[2+sub]);
                MMA_BF16(acc[mt][nt], ah[mt][0], ah[mt][1], ah[mt][2], ah[mt][3], bl[sub], bl[2+sub]);
                MMA_BF16(acc[mt][nt], al[mt][0], al[mt][1], al[mt][2], al[mt][3], bh[sub], bh[2+sub]);
            }
        }
    }
}

#define CPA(dst, src) \
    asm volatile("cp.async.cg.shared.global [%0], [%1], 16;" :: "r"(dst), "l"(src))

#define ISSUE_STAGE(s, b) {                                                       \
    unsigned d_ = smb + (unsigned)(b)*STG_B + (unsigned)(lr*48 + half*16);        \
    CPA(d_,         aH + (size_t)(s)*8);                                          \
    CPA(d_ + 6144u, aL + (size_t)(s)*8);                                          \
    if (t < 128) {                                                                \
        unsigned e_ = smb + (unsigned)(b)*STG_B + 12288u + (unsigned)(lr*48 + half*16); \
        CPA(e_,         bH + (size_t)(s)*8);                                      \
        CPA(e_ + 3072u, bL + (size_t)(s)*8);                                      \
    }                                                                             \
    asm volatile("cp.async.commit_group;" ::: "memory"); }

#define GEMM_LOOP(NS_) {                                                          \
    ISSUE_STAGE(0, 0);                                                            \
    ISSUE_STAGE(1, 1);                                                            \
    ISSUE_STAGE(2, 2);                                                            \
    for (int i = 0; i < (NS_); i++) {                                             \
        const int rem = (NS_) - 1 - i;                                            \
        if (rem >= 2)      { asm volatile("cp.async.wait_group 2;" ::: "memory"); }\
        else if (rem == 1) { asm volatile("cp.async.wait_group 1;" ::: "memory"); }\
        else               { asm volatile("cp.async.wait_group 0;" ::: "memory"); }\
        __syncthreads();                                                          \
        const unsigned bb = smb + (unsigned)(i & 3) * STG_B;                      \
        compute_stage(bb, bb + 6144u, bb + 12288u, bb + 15360u, wm, wn, lane, acc);\
        if (i + 3 < (NS_)) ISSUE_STAGE(i + 3, (i + 3) & 3);                       \
    } }

#define ISSUE_PV(s, b) {                                                          \
    unsigned d_ = smb + (unsigned)(b)*STG_PV + (unsigned)(lr*48 + half*16);       \
    CPA(d_,         aH + (size_t)(s)*8);                                          \
    CPA(d_ + 6144u, aL + (size_t)(s)*8);                                          \
    if (t < 128) {                                                                \
        unsigned e_ = smb + (unsigned)(b)*STG_PV + 12288u                         \
                    + (unsigned)((t>>3)*BPITCH + (t&7)*16);                       \
        CPA(e_,         vbh + (size_t)(s)*16*128);                                \
        CPA(e_ + 2304u, vbl + (size_t)(s)*16*128);                                \
    }                                                                             \
    asm volatile("cp.async.commit_group;" ::: "memory"); }

#define GEMM_LOOP_PV(NS_) {                                                       \
    ISSUE_PV(0, 0);                                                               \
    ISSUE_PV(1, 1);                                                               \
    ISSUE_PV(2, 2);                                                               \
    for (int i = 0; i < (NS_); i++) {                                             \
        const int rem = (NS_) - 1 - i;                                            \
        if (rem >= 2)      { asm volatile("cp.async.wait_group 2;" ::: "memory"); }\
        else if (rem == 1) { asm volatile("cp.async.wait_group 1;" ::: "memory"); }\
        else               { asm volatile("cp.async.wait_group 0;" ::: "memory"); }\
        __syncthreads();                                                          \
        const unsigned bb = smb + (unsigned)(i & 3) * STG_PV;                     \
        compute_stage_pv(bb, bb + 6144u, bb + 12288u, bb + 14592u, wm, wn, lane, acc);\
        if (i + 3 < (NS_)) ISSUE_PV(i + 3, (i + 3) & 3);                          \
    } }

// ---------------------------------------------------------------------------
// Kernel 0: pre-split all three fp32 operands -> hi/lo packed bf16 (one launch)
// ---------------------------------------------------------------------------
#define NXW  (TOK*ED/2)
#define NWAW (QKV*ED/2)
#define NWOW (ED*NE/2)
__global__ void __launch_bounds__(256) split_all(const float* __restrict__ x,
                                                 const float* __restrict__ wa,
                                                 const float* __restrict__ wo) {
    int i = blockIdx.x * 256 + threadIdx.x;
    const float* src; unsigned *H, *L; int j = i;
    if (j < NXW)              { src = x;  H = g_xh;  L = g_xl; }
    else if ((j -= NXW) < NWAW) { src = wa; H = g_wah; L = g_wal; }
    else if ((j -= NWAW) < NWOW){ src = wo; H = g_woh; L = g_wol; }
    else return;
    float2 v = ((const float2*)src)[j];
    unsigned h, l;
    split2(v.x, v.y, h, l);
    H[j] = h; L[j] = l;
}

// Q/K/V epilogue writer: raw-view remap baked in. row = global token, col in [0,2048)
__device__ __forceinline__ void write_qk(unsigned* H, unsigned* L, int row, int col,
                                         float v0, float v1) {
    int b = row >> 10, sp = row & 1023;
    int h = sp >> 7, s = ((sp & 127) << 3) + (col >> 8), d = col & 255;
    size_t idx = ((((size_t)(b*8 + h)) * SQL + s) << 7) + (d >> 1);
    unsigned hh, ll;
    split2(v0, v1, hh, ll);
    H[idx] = hh; L[idx] = ll;
}

// ---------------------------------------------------------------------------
// Kernel 1: proj = x @ w_attn^T + b_attn; scatters Q,K,V split-bf16
// ---------------------------------------------------------------------------
__global__ void __launch_bounds__(256, 3) proj_gemm(const float* __restrict__ bias) {
    extern __shared__ unsigned smd[];
    const unsigned smb = smem_u32(smd);
    const int m0 = blockIdx.y * BM, n0 = blockIdx.x * BN;
    const int t = threadIdx.x, lane = t & 31, w = t >> 5;
    const int wm = w >> 1, wn = w & 1;
    const int lr = t >> 1, half = t & 1;
    const unsigned* aH = g_xh  + (size_t)(m0 + lr) * 128 + half*4;
    const unsigned* aL = g_xl  + (size_t)(m0 + lr) * 128 + half*4;
    const unsigned* bH = g_wah + (size_t)(n0 + lr) * 128 + half*4;
    const unsigned* bL = g_wal + (size_t)(n0 + lr) * 128 + half*4;
    float acc[2][4][4] = {};
    GEMM_LOOP(ED/BK);

    const int g = lane >> 2, qq = lane & 3;
    #pragma unroll
    for (int mt = 0; mt < 2; mt++) {
        int row = m0 + wm*32 + mt*16 + g;
        #pragma unroll
        for (int nt = 0; nt < 4; nt++) {
            int col = n0 + wn*32 + nt*8 + qq*2;
            float bv0 = bias[col], bv1 = bias[col+1];
            float p0 = acc[mt][nt][0] + bv0, p1 = acc[mt][nt][1] + bv1;
            float p2 = acc[mt][nt][2] + bv0, p3 = acc[mt][nt][3] + bv1;
            unsigned *H, *L; int c;
            if (col < NE)          { H = g_qh; L = g_ql; c = col; }
            else if (col < 2*NE)   { H = g_kh; L = g_kl; c = col - NE; }
            else                   { H = g_vh; L = g_vl; c = col - 2*NE; }
            write_qk(H, L, row,   c, p0, p1);
            write_qk(H, L, row+8, c, p2, p3);
        }
    }
}

// ---------------------------------------------------------------------------
// Kernel 2: scores = (Q·K^T)/16; skip tiles fully above diagonal
// ---------------------------------------------------------------------------
__global__ void __launch_bounds__(256, 3) score_gemm() {
    const int q0 = blockIdx.y * BM, k0 = blockIdx.x * BN;
    if (k0 > q0 + (BM - 1)) return;
    const int bh = blockIdx.z;
    extern __shared__ unsigned smd[];
    const unsigned smb = smem_u32(smd);
    const int t = threadIdx.x, lane = t & 31, w = t >> 5;
    const int wm = w >> 1, wn = w & 1;
    const int lr = t >> 1, half = t & 1;
    const unsigned* aH = g_qh + ((size_t)bh * SQL + q0 + lr) * 128 + half*4;
    const unsigned* aL = g_ql + ((size_t)bh * SQL + q0 + lr) * 128 + half*4;
    const unsigned* bH = g_kh + ((size_t)bh * SQL + k0 + lr) * 128 + half*4;
    const unsigned* bL = g_kl + ((size_t)bh * SQL + k0 + lr) * 128 + half*4;
    float acc[2][4][4] = {};
    GEMM_LOOP(ED/BK);

    float* S = g_scores + (size_t)bh * SQL * SQL;
    const int g = lane >> 2, qq = lane & 3;
    #pragma unroll
    for (int mt = 0; mt < 2; mt++) {
        int row = q0 + wm*32 + mt*16 + g;
        #pragma unroll
        for (int nt = 0; nt < 4; nt++) {
            int col = k0 + wn*32 + nt*8 + qq*2;
            float* d0 = S + (size_t)row * SQL + col;
            float* d1 = S + (size_t)(row+8) * SQL + col;
            *(float2*)d0 = make_float2(acc[mt][nt][0]*0.0625f, acc[mt][nt][1]*0.0625f);
            *(float2*)d1 = make_float2(acc[mt][nt][2]*0.0625f, acc[mt][nt][3]*0.0625f);
        }
    }
}

// ---------------------------------------------------------------------------
// Kernel 3: causal softmax; touches only cols < kend = ceil((q+1)/128)*128.
// __expf: MUFU path (rel err ~1e-7, absorbed by split-bf16 error budget).
// ---------------------------------------------------------------------------
__global__ void __launch_bounds__(128) softmax_rows() {
    const int row = blockIdx.x;
    const int q = row & (SQL - 1);
    const int kend = ((q >> 7) + 1) << 7;
    const float* r = g_scores + (size_t)row * SQL;
    const int t = threadIdx.x;
    const int k0 = t * 8;
    const bool act = (k0 < kend);
    float v[8];
    float mx = -1e30f;
    if (act) {
        float4 x0 = *(const float4*)(r + k0);
        float4 x1 = *(const float4*)(r + k0 + 4);
        v[0]=x0.x; v[1]=x0.y; v[2]=x0.z; v[3]=x0.w;
        v[4]=x1.x; v[5]=x1.y; v[6]=x1.z; v[7]=x1.w;
        #pragma unroll
        for (int i = 0; i < 8; i++) {
            v[i] = (k0 + i <= q) ? v[i] : -1e30f;
            mx = fmaxf(mx, v[i]);
        }
    }
    __shared__ float redm[4], reds[4];
    #pragma unroll
    for (int o = 16; o > 0; o >>= 1) mx = fmaxf(mx, __shfl_xor_sync(0xffffffffu, mx, o));
    if ((t & 31) == 0) redm[t >> 5] = mx;
    __syncthreads();
    mx = fmaxf(fmaxf(redm[0], redm[1]), fmaxf(redm[2], redm[3]));
    float sum = 0.f;
    if (act) {
        #pragma unroll
        for (int i = 0; i < 8; i++) {
            v[i] = (k0 + i <= q) ? __expf(v[i] - mx) : 0.f;
            sum += v[i];
        }
    }
    #pragma unroll
    for (int o = 16; o > 0; o >>= 1) sum += __shfl_xor_sync(0xffffffffu, sum, o);
    if ((t & 31) == 0) reds[t >> 5] = sum;
    __syncthreads();
    sum = reds[0] + reds[1] + reds[2] + reds[3];
    if (act) {
        float inv = 1.f / sum;
        unsigned hh[4], ll[4];
        #pragma unroll
        for (int j = 0; j < 4; j++)
            split2(v[2*j] * inv, v[2*j+1] * inv, hh[j], ll[j]);
        *(uint4*)(g_ph + (size_t)row * 512 + t*4) = make_uint4(hh[0], hh[1], hh[2], hh[3]);
        *(uint4*)(g_pl + (size_t)row * 512 + t*4) = make_uint4(ll[0], ll[1], ll[2], ll[3]);
    }
}

// ---------------------------------------------------------------------------
// Kernel 4: O = P @ V (V natural layout, B frags via ldsm.trans); causal trunc
// ---------------------------------------------------------------------------
__global__ void __launch_bounds__(256, 3) pv_gemm() {
    const int bh = blockIdx.z;
    const int q0 = (int)(gridDim.y - 1 - blockIdx.y) * BM;   // heavy tiles first
    const int n0 = blockIdx.x * BN;
    extern __shared__ unsigned smd[];
    const unsigned smb = smem_u32(smd);
    const int t = threadIdx.x, lane = t & 31, w = t >> 5;
    const int wm = w >> 1, wn = w & 1;
    const int lr = t >> 1, half = t & 1;
    const int NS = (q0 + BM) / BK;
    const unsigned* aH = g_ph + ((size_t)bh * SQL + q0 + lr) * 512 + half*4;
    const unsigned* aL = g_pl + ((size_t)bh * SQL + q0 + lr) * 512 + half*4;
    const unsigned* vbh = g_vh + ((size_t)bh * SQL + (t>>3)) * 128 + (n0>>1) + (t&7)*4;
    const unsigned* vbl = g_vl + ((size_t)bh * SQL + (t>>3)) * 128 + (n0>>1) + (t&7)*4;
    float acc[2][4][4] = {};
    GEMM_LOOP_PV(NS);

    const int g = lane >> 2, qq = lane & 3;
    #pragma unroll
    for (int mt = 0; mt < 2; mt++) {
        int row = q0 + wm*32 + mt*16 + g;
        #pragma unroll
        for (int nt = 0; nt < 4; nt++) {
            int col = n0 + wn*32 + nt*8 + qq*2;
            size_t i0 = ((size_t)bh * SQL + row) * 128 + (col >> 1);
            size_t i1 = ((size_t)bh * SQL + row + 8) * 128 + (col >> 1);
            unsigned hh, ll;
            split2(acc[mt][nt][0], acc[mt][nt][1], hh, ll);
            g_ah[i0] = hh; g_al[i0] = ll;
            split2(acc[mt][nt][2], acc[mt][nt][3], hh, ll);
            g_ah[i1] = hh; g_al[i1] = ll;
        }
    }
}

// ---------------------------------------------------------------------------
// Kernel 5: out partials (split-K=3): z in {0,1,2}, k-chunks 43/43/42 stages
// ---------------------------------------------------------------------------
__global__ void __launch_bounds__(256, 3) out_gemm() {
    extern __shared__ unsigned smd[];
    const unsigned smb = smem_u32(smd);
    const int m0 = blockIdx.y * BM, n0 = blockIdx.x * BN;
    const int z = blockIdx.z;
    float* P = (z == 0) ? g_op0 : (z == 1) ? g_op1 : g_op2;
    const int kw0 = z * 43 * 8;                       // starting u32 word
    const int NSz = (z == 2) ? 42 : 43;
    const int t = threadIdx.x, lane = t & 31, w = t >> 5;
    const int wm = w >> 1, wn = w & 1;
    const int lr = t >> 1, half = t & 1;
    const unsigned* aH = g_ah  + (size_t)(m0 + lr) * 1024 + kw0 + half*4;
    const unsigned* aL = g_al  + (size_t)(m0 + lr) * 1024 + kw0 + half*4;
    const unsigned* bH = g_woh + (size_t)(n0 + lr) * 1024 + kw0 + half*4;
    const unsigned* bL = g_wol + (size_t)(n0 + lr) * 1024 + kw0 + half*4;
    float acc[2][4][4] = {};
    GEMM_LOOP(NSz);

    const int g = lane >> 2, qq = lane & 3;
    #pragma unroll
    for (int mt = 0; mt < 2; mt++) {
        int row = m0 + wm*32 + mt*16 + g;
        #pragma unroll
        for (int nt = 0; nt < 4; nt++) {
            int col = n0 + wn*32 + nt*8 + qq*2;
            *(float2*)(P + (size_t)row * ED + col) =
                make_float2(acc[mt][nt][0], acc[mt][nt][1]);
            *(float2*)(P + (size_t)(row+8) * ED + col) =
                make_float2(acc[mt][nt][2], acc[mt][nt][3]);
        }
    }
}

// Kernel 6: C = op0 + op1 + op2 + bias
__global__ void __launch_bounds__(256) out_reduce(const float* __restrict__ bias,
                                                  float* __restrict__ C) {
    int i = blockIdx.x * 256 + threadIdx.x;       // float4 index
    float4 a = ((const float4*)g_op0)[i];
    float4 b = ((const float4*)g_op1)[i];
    float4 c = ((const float4*)g_op2)[i];
    int col = (i * 4) & (ED - 1);
    float4 bb = *(const float4*)(bias + col);
    ((float4*)C)[i] = make_float4(a.x+b.x+c.x+bb.x, a.y+b.y+c.y+bb.y,
                                  a.z+b.z+c.z+bb.z, a.w+b.w+c.w+bb.w);
}

extern "C" void kernel_launch(void* const* d_in, const int* in_sizes, int n_in,
                              void* d_out, int out_size) {
    const float* x      = (const float*)d_in[0];
    const float* w_attn = (const float*)d_in[1];
    const float* b_attn = (const float*)d_in[2];
    const float* w_out  = (const float*)d_in[3];
    const float* b_out  = (const float*)d_in[4];
    float* out = (float*)d_out;

    cudaFuncSetAttribute(proj_gemm,  cudaFuncAttributeMaxDynamicSharedMemorySize, SMEM_SZ);
    cudaFuncSetAttribute(score_gemm, cudaFuncAttributeMaxDynamicSharedMemorySize, SMEM_SZ);
    cudaFuncSetAttribute(pv_gemm,    cudaFuncAttributeMaxDynamicSharedMemorySize, NPIPE*STG_PV);
    cudaFuncSetAttribute(out_gemm,   cudaFuncAttributeMaxDynamicSharedMemorySize, SMEM_SZ);

    const int NTOT = NXW + NWAW + NWOW;
    split_all<<<(NTOT + 255)/256, 256>>>(x, w_attn, w_out);

    proj_gemm<<<dim3(QKV/BN, TOK/BM), 256, SMEM_SZ>>>(b_attn);
    score_gemm<<<dim3(SQL/BN, SQL/BM, NBH), 256, SMEM_SZ>>>();
    softmax_rows<<<NBH*SQL, 128>>>();
    pv_gemm<<<dim3(ED/BN, SQL/BM, NBH), 256, NPIPE*STG_PV>>>();
    out_gemm<<<dim3(ED/BN, TOK/BM, 3), 256, SMEM_SZ>>>();
    out_reduce<<<TOK*ED/4/256, 256>>>(b_out, out);
}

// round 15
// speedup vs baseline: 1.1846x; 1.0167x over previous
#include <cuda_runtime.h>
#include <cuda_bf16.h>
#include <math.h>
#include <stdint.h>

#define NHH 8
#define ED 256
#define SQL 1024
#define BSZ 4
#define QKV (NHH*3*ED)   /* 6144 */
#define NE  (NHH*ED)     /* 2048 */
#define TOK (BSZ*SQL)    /* 4096 */
#define NBH (BSZ*NHH)    /* 32 */

// ---------------------------------------------------------------------------
// Device-global scratch. hi/lo split-bf16: packed u32 = (elem2i, elem2i+1).
// Q, K, V all stored natural [bh][s][d/2] (raw-view remap applied at write).
// ---------------------------------------------------------------------------
__device__ unsigned g_xh [(size_t)TOK*ED/2],  g_xl [(size_t)TOK*ED/2];
__device__ unsigned g_wah[(size_t)QKV*ED/2],  g_wal[(size_t)QKV*ED/2];
__device__ unsigned g_woh[(size_t)ED*NE/2],   g_wol[(size_t)ED*NE/2];
__device__ unsigned g_qh [(size_t)NBH*SQL*ED/2], g_ql [(size_t)NBH*SQL*ED/2];
__device__ unsigned g_kh [(size_t)NBH*SQL*ED/2], g_kl [(size_t)NBH*SQL*ED/2];
__device__ unsigned g_vh [(size_t)NBH*SQL*ED/2], g_vl [(size_t)NBH*SQL*ED/2];
__device__ unsigned g_ph [(size_t)NBH*SQL*SQL/2], g_pl [(size_t)NBH*SQL*SQL/2];
__device__ unsigned g_ah [(size_t)TOK*NE/2],  g_al [(size_t)TOK*NE/2];
__device__ float    g_scores[(size_t)NBH*SQL*SQL];
__device__ float    g_op0[(size_t)TOK*ED], g_op1[(size_t)TOK*ED], g_op2[(size_t)TOK*ED];

#define BM 128
#define BN 64          /* block tile 128x64; warp tile 32x32 */
#define BK 16
#define STRIDE 12      /* A/B(NT) smem rows: 8 used u32 + 4 pad */
#define STG_B 18432u   /* NT stage: A hi/lo 2x6144 + B hi/lo 2x3072 */
#define BPITCH 144u    /* pv B tile row pitch (128 B data + 16 pad) */
#define STG_PV 16896u  /* pv stage: A hi/lo 2x6144 + B hi/lo 2x2304 */
#define NPIPE 4
#define SMEM_SZ (NPIPE*18432)   /* 72 KB per CTA -> 3 CTAs/SM */

__device__ __forceinline__ unsigned smem_u32(const void* p) {
    unsigned a;
    asm("{ .reg .u64 t; cvta.to.shared.u64 t, %1; cvt.u32.u64 %0, t; }" : "=r"(a) : "l"(p));
    return a;
}

__device__ __forceinline__ void split2(float a, float b, unsigned &h, unsigned &l) {
    __nv_bfloat16 ah = __float2bfloat16(a), bh = __float2bfloat16(b);
    float ar = a - __bfloat162float(ah);
    float br = b - __bfloat162float(bh);
    __nv_bfloat16 al = __float2bfloat16(ar), bl = __float2bfloat16(br);
    h = (unsigned)__bfloat16_as_ushort(ah) | ((unsigned)__bfloat16_as_ushort(bh) << 16);
    l = (unsigned)__bfloat16_as_ushort(al) | ((unsigned)__bfloat16_as_ushort(bl) << 16);
}

#define MMA_BF16(C, A0, A1, A2, A3, B0, B1)                                      \
    asm volatile("mma.sync.aligned.m16n8k16.row.col.f32.bf16.bf16.f32 "          \
        "{%0,%1,%2,%3}, {%4,%5,%6,%7}, {%8,%9}, {%0,%1,%2,%3};"                  \
        : "+f"((C)[0]), "+f"((C)[1]), "+f"((C)[2]), "+f"((C)[3])                  \
        : "r"(A0), "r"(A1), "r"(A2), "r"(A3), "r"(B0), "r"(B1))

__device__ __forceinline__ void ldsm4(unsigned addr, unsigned r[4]) {
    asm volatile("ldmatrix.sync.aligned.m8n8.x4.shared.b16 {%0,%1,%2,%3}, [%4];"
        : "=r"(r[0]), "=r"(r[1]), "=r"(r[2]), "=r"(r[3]) : "r"(addr));
}
__device__ __forceinline__ void ldsm4t(unsigned addr, unsigned r[4]) {
    asm volatile("ldmatrix.sync.aligned.m8n8.x4.trans.shared.b16 {%0,%1,%2,%3}, [%4];"
        : "=r"(r[0]), "=r"(r[1]), "=r"(r[2]), "=r"(r[3]) : "r"(addr));
}

// NT stage: B tile rows = n (8 u32 along k), non-trans ldsm. Warp tile 32x32.
// MMA emission order: split-term outermost -> dependent updates of each
// accumulator are separated by 4 independent MMAs (ILP for HMMA RAW latency).
// Per-accumulator term order unchanged (hh, hl, lh) -> bit-identical results.
__device__ __forceinline__ void compute_stage(
    unsigned Ah, unsigned Al, unsigned Bh, unsigned Bl,
    int wm, int wn, int lane, float acc[2][4][4])
{
    const int lrow = (lane & 7) | (((lane >> 3) & 1) << 3);
    const int lcw  = (lane >> 4) * 4;
    const unsigned aoff = (unsigned)(((wm*32 + lrow) * STRIDE + lcw) * 4);
    const unsigned boff = (unsigned)(((wn*32 + lrow) * STRIDE + lcw) * 4);

    unsigned ah[2][4], al[2][4];
    #pragma unroll
    for (int mt = 0; mt < 2; mt++) {
        ldsm4(Ah + aoff + (unsigned)(mt*16*STRIDE*4), ah[mt]);
        ldsm4(Al + aoff + (unsigned)(mt*16*STRIDE*4), al[mt]);
    }
    #pragma unroll
    for (int ntp = 0; ntp < 2; ntp++) {
        unsigned bh[4], bl[4];
        ldsm4(Bh + boff + (unsigned)(ntp*16*STRIDE*4), bh);
        ldsm4(Bl + boff + (unsigned)(ntp*16*STRIDE*4), bl);
        #pragma unroll
        for (int sub = 0; sub < 2; sub++)
            #pragma unroll
            for (int mt = 0; mt < 2; mt++)
                MMA_BF16(acc[mt][ntp*2+sub], ah[mt][0], ah[mt][1], ah[mt][2], ah[mt][3], bh[sub], bh[2+sub]);
        #pragma unroll
        for (int sub = 0; sub < 2; sub++)
            #pragma unroll
            for (int mt = 0; mt < 2; mt++)
                MMA_BF16(acc[mt][ntp*2+sub], ah[mt][0], ah[mt][1], ah[mt][2], ah[mt][3], bl[sub], bl[2+sub]);
        #pragma unroll
        for (int sub = 0; sub < 2; sub++)
            #pragma unroll
            for (int mt = 0; mt < 2; mt++)
                MMA_BF16(acc[mt][ntp*2+sub], al[mt][0], al[mt][1], al[mt][2], al[mt][3], bh[sub], bh[2+sub]);
    }
}

// PV stage: B tile rows = k (16 rows x 128B bf16 along n=d, pitch 144B), trans ldsm.
__device__ __forceinline__ void compute_stage_pv(
    unsigned Ah, unsigned Al, unsigned Bh, unsigned Bl,
    int wm, int wn, int lane, float acc[2][4][4])
{
    const int lrow = (lane & 7) | (((lane >> 3) & 1) << 3);
    const int lcw  = (lane >> 4) * 4;
    const unsigned aoff = (unsigned)(((wm*32 + lrow) * STRIDE + lcw) * 4);
    const int bk  = ((lane >> 4) & 1) * 8 + (lane & 7);
    const int bnh = (lane >> 3) & 1;
    const unsigned boff = (unsigned)(bk * BPITCH + (unsigned)(wn*64 + bnh*16));

    unsigned ah[2][4], al[2][4];
    #pragma unroll
    for (int mt = 0; mt < 2; mt++) {
        ldsm4(Ah + aoff + (unsigned)(mt*16*STRIDE*4), ah[mt]);
        ldsm4(Al + aoff + (unsigned)(mt*16*STRIDE*4), al[mt]);
    }
    #pragma unroll
    for (int ntp = 0; ntp < 2; ntp++) {
        unsigned bh[4], bl[4];
        ldsm4t(Bh + boff + (unsigned)(ntp*32), bh);
        ldsm4t(Bl + boff + (unsigned)(ntp*32), bl);
        #pragma unroll
        for (int sub = 0; sub < 2; sub++)
            #pragma unroll
            for (int mt = 0; mt < 2; mt++)
                MMA_BF16(acc[mt][ntp*2+sub], ah[mt][0], ah[mt][1], ah[mt][2], ah[mt][3], bh[sub], bh[2+sub]);
        #pragma unroll
        for (int sub = 0; sub < 2; sub++)
            #pragma unroll
            for (int mt = 0; mt < 2; mt++)
                MMA_BF16(acc[mt][ntp*2+sub], ah[mt][0], ah[mt][1], ah[mt][2], ah[mt][3], bl[sub], bl[2+sub]);
        #pragma unroll
        for (int sub = 0; sub < 2; sub++)
            #pragma unroll
            for (int mt = 0; mt < 2; mt++)
                MMA_BF16(acc[mt][ntp*2+sub], al[mt][0], al[mt][1], al[mt][2], al[mt][3], bh[sub], bh[2+sub]);
    }
}

#define CPA(dst, src) \
    asm volatile("cp.async.cg.shared.global [%0], [%1], 16;" :: "r"(dst), "l"(src))

#define ISSUE_STAGE(s, b) {                                                       \
    unsigned d_ = smb + (unsigned)(b)*STG_B + (unsigned)(lr*48 + half*16);        \
    CPA(d_,         aH + (size_t)(s)*8);                                          \
    CPA(d_ + 6144u, aL + (size_t)(s)*8);                                          \
    if (t < 128) {                                                                \
        unsigned e_ = smb + (unsigned)(b)*STG_B + 12288u + (unsigned)(lr*48 + half*16); \
        CPA(e_,         bH + (size_t)(s)*8);                                      \
        CPA(e_ + 3072u, bL + (size_t)(s)*8);                                      \
    }                                                                             \
    asm volatile("cp.async.commit_group;" ::: "memory"); }

#define GEMM_LOOP(NS_) {                                                          \
    ISSUE_STAGE(0, 0);                                                            \
    ISSUE_STAGE(1, 1);                                                            \
    ISSUE_STAGE(2, 2);                                                            \
    for (int i = 0; i < (NS_); i++) {                                             \
        const int rem = (NS_) - 1 - i;                                            \
        if (rem >= 2)      { asm volatile("cp.async.wait_group 2;" ::: "memory"); }\
        else if (rem == 1) { asm volatile("cp.async.wait_group 1;" ::: "memory"); }\
        else               { asm volatile("cp.async.wait_group 0;" ::: "memory"); }\
        __syncthreads();                                                          \
        const unsigned bb = smb + (unsigned)(i & 3) * STG_B;                      \
        compute_stage(bb, bb + 6144u, bb + 12288u, bb + 15360u, wm, wn, lane, acc);\
        if (i + 3 < (NS_)) ISSUE_STAGE(i + 3, (i + 3) & 3);                       \
    } }

#define ISSUE_PV(s, b) {                                                          \
    unsigned d_ = smb + (unsigned)(b)*STG_PV + (unsigned)(lr*48 + half*16);       \
    CPA(d_,         aH + (size_t)(s)*8);                                          \
    CPA(d_ + 6144u, aL + (size_t)(s)*8);                                          \
    if (t < 128) {                                                                \
        unsigned e_ = smb + (unsigned)(b)*STG_PV + 12288u                         \
                    + (unsigned)((t>>3)*BPITCH + (t&7)*16);                       \
        CPA(e_,         vbh + (size_t)(s)*16*128);                                \
        CPA(e_ + 2304u, vbl + (size_t)(s)*16*128);                                \
    }                                                                             \
    asm volatile("cp.async.commit_group;" ::: "memory"); }

#define GEMM_LOOP_PV(NS_) {                                                       \
    ISSUE_PV(0, 0);                                                               \
    ISSUE_PV(1, 1);                                                               \
    ISSUE_PV(2, 2);                                                               \
    for (int i = 0; i < (NS_); i++) {                                             \
        const int rem = (NS_) - 1 - i;                                            \
        if (rem >= 2)      { asm volatile("cp.async.wait_group 2;" ::: "memory"); }\
        else if (rem == 1) { asm volatile("cp.async.wait_group 1;" ::: "memory"); }\
        else               { asm volatile("cp.async.wait_group 0;" ::: "memory"); }\
        __syncthreads();                                                          \
        const unsigned bb = smb + (unsigned)(i & 3) * STG_PV;                     \
        compute_stage_pv(bb, bb + 6144u, bb + 12288u, bb + 14592u, wm, wn, lane, acc);\
        if (i + 3 < (NS_)) ISSUE_PV(i + 3, (i + 3) & 3);                          \
    } }

// ---------------------------------------------------------------------------
// Kernel 0: pre-split all three fp32 operands -> hi/lo packed bf16 (one launch)
// ---------------------------------------------------------------------------
#define NXW  (TOK*ED/2)
#define NWAW (QKV*ED/2)
#define NWOW (ED*NE/2)
__global__ void __launch_bounds__(256) split_all(const float* __restrict__ x,
                                                 const float* __restrict__ wa,
                                                 const float* __restrict__ wo) {
    int i = blockIdx.x * 256 + threadIdx.x;
    const float* src; unsigned *H, *L; int j = i;
    if (j < NXW)              { src = x;  H = g_xh;  L = g_xl; }
    else if ((j -= NXW) < NWAW) { src = wa; H = g_wah; L = g_wal; }
    else if ((j -= NWAW) < NWOW){ src = wo; H = g_woh; L = g_wol; }
    else return;
    float2 v = ((const float2*)src)[j];
    unsigned h, l;
    split2(v.x, v.y, h, l);
    H[j] = h; L[j] = l;
}

// Q/K/V epilogue writer: raw-view remap baked in. row = global token, col in [0,2048)
__device__ __forceinline__ void write_qk(unsigned* H, unsigned* L, int row, int col,
                                         float v0, float v1) {
    int b = row >> 10, sp = row & 1023;
    int h = sp >> 7, s = ((sp & 127) << 3) + (col >> 8), d = col & 255;
    size_t idx = ((((size_t)(b*8 + h)) * SQL + s) << 7) + (d >> 1);
    unsigned hh, ll;
    split2(v0, v1, hh, ll);
    H[idx] = hh; L[idx] = ll;
}

// ---------------------------------------------------------------------------
// Kernel 1: proj = x @ w_attn^T + b_attn; scatters Q,K,V split-bf16
// ---------------------------------------------------------------------------
__global__ void __launch_bounds__(256, 3) proj_gemm(const float* __restrict__ bias) {
    extern __shared__ unsigned smd[];
    const unsigned smb = smem_u32(smd);
    const int m0 = blockIdx.y * BM, n0 = blockIdx.x * BN;
    const int t = threadIdx.x, lane = t & 31, w = t >> 5;
    const int wm = w >> 1, wn = w & 1;
    const int lr = t >> 1, half = t & 1;
    const unsigned* aH = g_xh  + (size_t)(m0 + lr) * 128 + half*4;
    const unsigned* aL = g_xl  + (size_t)(m0 + lr) * 128 + half*4;
    const unsigned* bH = g_wah + (size_t)(n0 + lr) * 128 + half*4;
    const unsigned* bL = g_wal + (size_t)(n0 + lr) * 128 + half*4;
    float acc[2][4][4] = {};
    GEMM_LOOP(ED/BK);

    const int g = lane >> 2, qq = lane & 3;
    #pragma unroll
    for (int mt = 0; mt < 2; mt++) {
        int row = m0 + wm*32 + mt*16 + g;
        #pragma unroll
        for (int nt = 0; nt < 4; nt++) {
            int col = n0 + wn*32 + nt*8 + qq*2;
            float bv0 = bias[col], bv1 = bias[col+1];
            float p0 = acc[mt][nt][0] + bv0, p1 = acc[mt][nt][1] + bv1;
            float p2 = acc[mt][nt][2] + bv0, p3 = acc[mt][nt][3] + bv1;
            unsigned *H, *L; int c;
            if (col < NE)          { H = g_qh; L = g_ql; c = col; }
            else if (col < 2*NE)   { H = g_kh; L = g_kl; c = col - NE; }
            else                   { H = g_vh; L = g_vl; c = col - 2*NE; }
            write_qk(H, L, row,   c, p0, p1);
            write_qk(H, L, row+8, c, p2, p3);
        }
    }
}

// ---------------------------------------------------------------------------
// Kernel 2: scores = (Q·K^T)/16; skip tiles fully above diagonal
// ---------------------------------------------------------------------------
__global__ void __launch_bounds__(256, 3) score_gemm() {
    const int q0 = blockIdx.y * BM, k0 = blockIdx.x * BN;
    if (k0 > q0 + (BM - 1)) return;
    const int bh = blockIdx.z;
    extern __shared__ unsigned smd[];
    const unsigned smb = smem_u32(smd);
    const int t = threadIdx.x, lane = t & 31, w = t >> 5;
    const int wm = w >> 1, wn = w & 1;
    const int lr = t >> 1, half = t & 1;
    const unsigned* aH = g_qh + ((size_t)bh * SQL + q0 + lr) * 128 + half*4;
    const unsigned* aL = g_ql + ((size_t)bh * SQL + q0 + lr) * 128 + half*4;
    const unsigned* bH = g_kh + ((size_t)bh * SQL + k0 + lr) * 128 + half*4;
    const unsigned* bL = g_kl + ((size_t)bh * SQL + k0 + lr) * 128 + half*4;
    float acc[2][4][4] = {};
    GEMM_LOOP(ED/BK);

    float* S = g_scores + (size_t)bh * SQL * SQL;
    const int g = lane >> 2, qq = lane & 3;
    #pragma unroll
    for (int mt = 0; mt < 2; mt++) {
        int row = q0 + wm*32 + mt*16 + g;
        #pragma unroll
        for (int nt = 0; nt < 4; nt++) {
            int col = k0 + wn*32 + nt*8 + qq*2;
            float* d0 = S + (size_t)row * SQL + col;
            float* d1 = S + (size_t)(row+8) * SQL + col;
            *(float2*)d0 = make_float2(acc[mt][nt][0]*0.0625f, acc[mt][nt][1]*0.0625f);
            *(float2*)d1 = make_float2(acc[mt][nt][2]*0.0625f, acc[mt][nt][3]*0.0625f);
        }
    }
}

// ---------------------------------------------------------------------------
// Kernel 3: causal softmax; touches only cols < kend = ceil((q+1)/128)*128.
// ---------------------------------------------------------------------------
__global__ void __launch_bounds__(128) softmax_rows() {
    const int row = blockIdx.x;
    const int q = row & (SQL - 1);
    const int kend = ((q >> 7) + 1) << 7;
    const float* r = g_scores + (size_t)row * SQL;
    const int t = threadIdx.x;
    const int k0 = t * 8;
    const bool act = (k0 < kend);
    float v[8];
    float mx = -1e30f;
    if (act) {
        float4 x0 = *(const float4*)(r + k0);
        float4 x1 = *(const float4*)(r + k0 + 4);
        v[0]=x0.x; v[1]=x0.y; v[2]=x0.z; v[3]=x0.w;
        v[4]=x1.x; v[5]=x1.y; v[6]=x1.z; v[7]=x1.w;
        #pragma unroll
        for (int i = 0; i < 8; i++) {
            v[i] = (k0 + i <= q) ? v[i] : -1e30f;
            mx = fmaxf(mx, v[i]);
        }
    }
    __shared__ float redm[4], reds[4];
    #pragma unroll
    for (int o = 16; o > 0; o >>= 1) mx = fmaxf(mx, __shfl_xor_sync(0xffffffffu, mx, o));
    if ((t & 31) == 0) redm[t >> 5] = mx;
    __syncthreads();
    mx = fmaxf(fmaxf(redm[0], redm[1]), fmaxf(redm[2], redm[3]));
    float sum = 0.f;
    if (act) {
        #pragma unroll
        for (int i = 0; i < 8; i++) {
            v[i] = (k0 + i <= q) ? __expf(v[i] - mx) : 0.f;
            sum += v[i];
        }
    }
    #pragma unroll
    for (int o = 16; o > 0; o >>= 1) sum += __shfl_xor_sync(0xffffffffu, sum, o);
    if ((t & 31) == 0) reds[t >> 5] = sum;
    __syncthreads();
    sum = reds[0] + reds[1] + reds[2] + reds[3];
    if (act) {
        float inv = 1.f / sum;
        unsigned hh[4], ll[4];
        #pragma unroll
        for (int j = 0; j < 4; j++)
            split2(v[2*j] * inv, v[2*j+1] * inv, hh[j], ll[j]);
        *(uint4*)(g_ph + (size_t)row * 512 + t*4) = make_uint4(hh[0], hh[1], hh[2], hh[3]);
        *(uint4*)(g_pl + (size_t)row * 512 + t*4) = make_uint4(ll[0], ll[1], ll[2], ll[3]);
    }
}

// ---------------------------------------------------------------------------
// Kernel 4: O = P @ V (V natural layout, B frags via ldsm.trans); causal trunc
// ---------------------------------------------------------------------------
__global__ void __launch_bounds__(256, 3) pv_gemm() {
    const int bh = blockIdx.z;
    const int q0 = (int)(gridDim.y - 1 - blockIdx.y) * BM;   // heavy tiles first
    const int n0 = blockIdx.x * BN;
    extern __shared__ unsigned smd[];
    const unsigned smb = smem_u32(smd);
    const int t = threadIdx.x, lane = t & 31, w = t >> 5;
    const int wm = w >> 1, wn = w & 1;
    const int lr = t >> 1, half = t & 1;
    const int NS = (q0 + BM) / BK;
    const unsigned* aH = g_ph + ((size_t)bh * SQL + q0 + lr) * 512 + half*4;
    const unsigned* aL = g_pl + ((size_t)bh * SQL + q0 + lr) * 512 + half*4;
    const unsigned* vbh = g_vh + ((size_t)bh * SQL + (t>>3)) * 128 + (n0>>1) + (t&7)*4;
    const unsigned* vbl = g_vl + ((size_t)bh * SQL + (t>>3)) * 128 + (n0>>1) + (t&7)*4;
    float acc[2][4][4] = {};
    GEMM_LOOP_PV(NS);

    const int g = lane >> 2, qq = lane & 3;
    #pragma unroll
    for (int mt = 0; mt < 2; mt++) {
        int row = q0 + wm*32 + mt*16 + g;
        #pragma unroll
        for (int nt = 0; nt < 4; nt++) {
            int col = n0 + wn*32 + nt*8 + qq*2;
            size_t i0 = ((size_t)bh * SQL + row) * 128 + (col >> 1);
            size_t i1 = ((size_t)bh * SQL + row + 8) * 128 + (col >> 1);
            unsigned hh, ll;
            split2(acc[mt][nt][0], acc[mt][nt][1], hh, ll);
            g_ah[i0] = hh; g_al[i0] = ll;
            split2(acc[mt][nt][2], acc[mt][nt][3], hh, ll);
            g_ah[i1] = hh; g_al[i1] = ll;
        }
    }
}

// ---------------------------------------------------------------------------
// Kernel 5: out partials (split-K=3): z in {0,1,2}, k-chunks 43/43/42 stages
// ---------------------------------------------------------------------------
__global__ void __launch_bounds__(256, 3) out_gemm() {
    extern __shared__ unsigned smd[];
    const unsigned smb = smem_u32(smd);
    const int m0 = blockIdx.y * BM, n0 = blockIdx.x * BN;
    const int z = blockIdx.z;
    float* P = (z == 0) ? g_op0 : (z == 1) ? g_op1 : g_op2;
    const int kw0 = z * 43 * 8;
    const int NSz = (z == 2) ? 42 : 43;
    const int t = threadIdx.x, lane = t & 31, w = t >> 5;
    const int wm = w >> 1, wn = w & 1;
    const int lr = t >> 1, half = t & 1;
    const unsigned* aH = g_ah  + (size_t)(m0 + lr) * 1024 + kw0 + half*4;
    const unsigned* aL = g_al  + (size_t)(m0 + lr) * 1024 + kw0 + half*4;
    const unsigned* bH = g_woh + (size_t)(n0 + lr) * 1024 + kw0 + half*4;
    const unsigned* bL = g_wol + (size_t)(n0 + lr) * 1024 + kw0 + half*4;
    float acc[2][4][4] = {};
    GEMM_LOOP(NSz);

    const int g = lane >> 2, qq = lane & 3;
    #pragma unroll
    for (int mt = 0; mt < 2; mt++) {
        int row = m0 + wm*32 + mt*16 + g;
        #pragma unroll
        for (int nt = 0; nt < 4; nt++) {
            int col = n0 + wn*32 + nt*8 + qq*2;
            *(float2*)(P + (size_t)row * ED + col) =
                make_float2(acc[mt][nt][0], acc[mt][nt][1]);
            *(float2*)(P + (size_t)(row+8) * ED + col) =
                make_float2(acc[mt][nt][2], acc[mt][nt][3]);
        }
    }
}

// Kernel 6: C = op0 + op1 + op2 + bias
__global__ void __launch_bounds__(256) out_reduce(const float* __restrict__ bias,
                                                  float* __restrict__ C) {
    int i = blockIdx.x * 256 + threadIdx.x;
    float4 a = ((const float4*)g_op0)[i];
    float4 b = ((const float4*)g_op1)[i];
    float4 c = ((const float4*)g_op2)[i];
    int col = (i * 4) & (ED - 1);
    float4 bb = *(const float4*)(bias + col);
    ((float4*)C)[i] = make_float4(a.x+b.x+c.x+bb.x, a.y+b.y+c.y+bb.y,
                                  a.z+b.z+c.z+bb.z, a.w+b.w+c.w+bb.w);
}

extern "C" void kernel_launch(void* const* d_in, const int* in_sizes, int n_in,
                              void* d_out, int out_size) {
    const float* x      = (const float*)d_in[0];
    const float* w_attn = (const float*)d_in[1];
    const float* b_attn = (const float*)d_in[2];
    const float* w_out  = (const float*)d_in[3];
    const float* b_out  = (const float*)d_in[4];
    float* out = (float*)d_out;

    cudaFuncSetAttribute(proj_gemm,  cudaFuncAttributeMaxDynamicSharedMemorySize, SMEM_SZ);
    cudaFuncSetAttribute(score_gemm, cudaFuncAttributeMaxDynamicSharedMemorySize, SMEM_SZ);
    cudaFuncSetAttribute(pv_gemm,    cudaFuncAttributeMaxDynamicSharedMemorySize, NPIPE*STG_PV);
    cudaFuncSetAttribute(out_gemm,   cudaFuncAttributeMaxDynamicSharedMemorySize, SMEM_SZ);

    const int NTOT = NXW + NWAW + NWOW;
    split_all<<<(NTOT + 255)/256, 256>>>(x, w_attn, w_out);

    proj_gemm<<<dim3(QKV/BN, TOK/BM), 256, SMEM_SZ>>>(b_attn);
    score_gemm<<<dim3(SQL/BN, SQL/BM, NBH), 256, SMEM_SZ>>>();
    softmax_rows<<<NBH*SQL, 128>>>();
    pv_gemm<<<dim3(ED/BN, SQL/BM, NBH), 256, NPIPE*STG_PV>>>();
    out_gemm<<<dim3(ED/BN, TOK/BM, 3), 256, SMEM_SZ>>>();
    out_reduce<<<TOK*ED/4/256, 256>>>(b_out, out);
}

// round 17
// speedup vs baseline: 1.2378x; 1.0450x over previous
#include <cuda_runtime.h>
#include <cuda_bf16.h>
#include <math.h>
#include <stdint.h>

#define NHH 8
#define ED 256
#define SQL 1024
#define BSZ 4
#define QKV (NHH*3*ED)   /* 6144 */
#define NE  (NHH*ED)     /* 2048 */
#define TOK (BSZ*SQL)    /* 4096 */
#define NBH (BSZ*NHH)    /* 32 */

// ---------------------------------------------------------------------------
// Device-global scratch. hi/lo split-bf16: packed u32 = (elem2i, elem2i+1).
// Q, K, V all stored natural [bh][s][d/2] (raw-view remap applied at write).
// ---------------------------------------------------------------------------
__device__ unsigned g_xh [(size_t)TOK*ED/2],  g_xl [(size_t)TOK*ED/2];
__device__ unsigned g_wah[(size_t)QKV*ED/2],  g_wal[(size_t)QKV*ED/2];
__device__ unsigned g_woh[(size_t)ED*NE/2],   g_wol[(size_t)ED*NE/2];
__device__ unsigned g_qh [(size_t)NBH*SQL*ED/2], g_ql [(size_t)NBH*SQL*ED/2];
__device__ unsigned g_kh [(size_t)NBH*SQL*ED/2], g_kl [(size_t)NBH*SQL*ED/2];
__device__ unsigned g_vh [(size_t)NBH*SQL*ED/2], g_vl [(size_t)NBH*SQL*ED/2];
__device__ unsigned g_ph [(size_t)NBH*SQL*SQL/2], g_pl [(size_t)NBH*SQL*SQL/2];
__device__ unsigned g_ah [(size_t)TOK*NE/2],  g_al [(size_t)TOK*NE/2];
__device__ float    g_scores[(size_t)NBH*SQL*SQL];
__device__ float    g_op0[(size_t)TOK*ED], g_op1[(size_t)TOK*ED], g_op2[(size_t)TOK*ED];

#define BM 128
#define BN 64          /* block tile 128x64; warp tile 32x32 */
#define BK 16
#define STRIDE 12      /* A/B(NT) smem rows: 8 used u32 + 4 pad */
#define STG_B 18432u   /* NT stage: A hi/lo 2x6144 + B hi/lo 2x3072 */
#define BPITCH 144u    /* pv B tile row pitch (128 B data + 16 pad) */
#define STG_PV 16896u  /* pv stage: A hi/lo 2x6144 + B hi/lo 2x2304 */
#define NPIPE 4
#define SMEM_SZ (NPIPE*18432)   /* 72 KB per CTA -> 3 CTAs/SM */

__device__ __forceinline__ unsigned smem_u32(const void* p) {
    unsigned a;
    asm("{ .reg .u64 t; cvta.to.shared.u64 t, %1; cvt.u32.u64 %0, t; }" : "=r"(a) : "l"(p));
    return a;
}

__device__ __forceinline__ void split2(float a, float b, unsigned &h, unsigned &l) {
    __nv_bfloat16 ah = __float2bfloat16(a), bh = __float2bfloat16(b);
    float ar = a - __bfloat162float(ah);
    float br = b - __bfloat162float(bh);
    __nv_bfloat16 al = __float2bfloat16(ar), bl = __float2bfloat16(br);
    h = (unsigned)__bfloat16_as_ushort(ah) | ((unsigned)__bfloat16_as_ushort(bh) << 16);
    l = (unsigned)__bfloat16_as_ushort(al) | ((unsigned)__bfloat16_as_ushort(bl) << 16);
}

#define MMA_BF16(C, A0, A1, A2, A3, B0, B1)                                      \
    asm volatile("mma.sync.aligned.m16n8k16.row.col.f32.bf16.bf16.f32 "          \
        "{%0,%1,%2,%3}, {%4,%5,%6,%7}, {%8,%9}, {%0,%1,%2,%3};"                  \
        : "+f"((C)[0]), "+f"((C)[1]), "+f"((C)[2]), "+f"((C)[3])                  \
        : "r"(A0), "r"(A1), "r"(A2), "r"(A3), "r"(B0), "r"(B1))

__device__ __forceinline__ void ldsm4(unsigned addr, unsigned r[4]) {
    asm volatile("ldmatrix.sync.aligned.m8n8.x4.shared.b16 {%0,%1,%2,%3}, [%4];"
        : "=r"(r[0]), "=r"(r[1]), "=r"(r[2]), "=r"(r[3]) : "r"(addr));
}
__device__ __forceinline__ void ldsm4t(unsigned addr, unsigned r[4]) {
    asm volatile("ldmatrix.sync.aligned.m8n8.x4.trans.shared.b16 {%0,%1,%2,%3}, [%4];"
        : "=r"(r[0]), "=r"(r[1]), "=r"(r[2]), "=r"(r[3]) : "r"(addr));
}

// NT stage: B tile rows = n (8 u32 along k), non-trans ldsm. Warp tile 32x32.
// MMA emission: split-term outermost (4 independent MMAs between dependent
// accumulator updates); per-accumulator term order hh,hl,lh (bit-identical).
__device__ __forceinline__ void compute_stage(
    unsigned Ah, unsigned Al, unsigned Bh, unsigned Bl,
    int wm, int wn, int lane, float acc[2][4][4])
{
    const int lrow = (lane & 7) | (((lane >> 3) & 1) << 3);
    const int lcw  = (lane >> 4) * 4;
    const unsigned aoff = (unsigned)(((wm*32 + lrow) * STRIDE + lcw) * 4);
    const unsigned boff = (unsigned)(((wn*32 + lrow) * STRIDE + lcw) * 4);

    unsigned ah[2][4], al[2][4];
    #pragma unroll
    for (int mt = 0; mt < 2; mt++) {
        ldsm4(Ah + aoff + (unsigned)(mt*16*STRIDE*4), ah[mt]);
        ldsm4(Al + aoff + (unsigned)(mt*16*STRIDE*4), al[mt]);
    }
    #pragma unroll
    for (int ntp = 0; ntp < 2; ntp++) {
        unsigned bh[4], bl[4];
        ldsm4(Bh + boff + (unsigned)(ntp*16*STRIDE*4), bh);
        ldsm4(Bl + boff + (unsigned)(ntp*16*STRIDE*4), bl);
        #pragma unroll
        for (int sub = 0; sub < 2; sub++)
            #pragma unroll
            for (int mt = 0; mt < 2; mt++)
                MMA_BF16(acc[mt][ntp*2+sub], ah[mt][0], ah[mt][1], ah[mt][2], ah[mt][3], bh[sub], bh[2+sub]);
        #pragma unroll
        for (int sub = 0; sub < 2; sub++)
            #pragma unroll
            for (int mt = 0; mt < 2; mt++)
                MMA_BF16(acc[mt][ntp*2+sub], ah[mt][0], ah[mt][1], ah[mt][2], ah[mt][3], bl[sub], bl[2+sub]);
        #pragma unroll
        for (int sub = 0; sub < 2; sub++)
            #pragma unroll
            for (int mt = 0; mt < 2; mt++)
                MMA_BF16(acc[mt][ntp*2+sub], al[mt][0], al[mt][1], al[mt][2], al[mt][3], bh[sub], bh[2+sub]);
    }
}

// PV stage: B tile rows = k (16 rows x 128B bf16 along n=d, pitch 144B), trans ldsm.
__device__ __forceinline__ void compute_stage_pv(
    unsigned Ah, unsigned Al, unsigned Bh, unsigned Bl,
    int wm, int wn, int lane, float acc[2][4][4])
{
    const int lrow = (lane & 7) | (((lane >> 3) & 1) << 3);
    const int lcw  = (lane >> 4) * 4;
    const unsigned aoff = (unsigned)(((wm*32 + lrow) * STRIDE + lcw) * 4);
    const int bk  = ((lane >> 4) & 1) * 8 + (lane & 7);
    const int bnh = (lane >> 3) & 1;
    const unsigned boff = (unsigned)(bk * BPITCH + (unsigned)(wn*64 + bnh*16));

    unsigned ah[2][4], al[2][4];
    #pragma unroll
    for (int mt = 0; mt < 2; mt++) {
        ldsm4(Ah + aoff + (unsigned)(mt*16*STRIDE*4), ah[mt]);
        ldsm4(Al + aoff + (unsigned)(mt*16*STRIDE*4), al[mt]);
    }
    #pragma unroll
    for (int ntp = 0; ntp < 2; ntp++) {
        unsigned bh[4], bl[4];
        ldsm4t(Bh + boff + (unsigned)(ntp*32), bh);
        ldsm4t(Bl + boff + (unsigned)(ntp*32), bl);
        #pragma unroll
        for (int sub = 0; sub < 2; sub++)
            #pragma unroll
            for (int mt = 0; mt < 2; mt++)
                MMA_BF16(acc[mt][ntp*2+sub], ah[mt][0], ah[mt][1], ah[mt][2], ah[mt][3], bh[sub], bh[2+sub]);
        #pragma unroll
        for (int sub = 0; sub < 2; sub++)
            #pragma unroll
            for (int mt = 0; mt < 2; mt++)
                MMA_BF16(acc[mt][ntp*2+sub], ah[mt][0], ah[mt][1], ah[mt][2], ah[mt][3], bl[sub], bl[2+sub]);
        #pragma unroll
        for (int sub = 0; sub < 2; sub++)
            #pragma unroll
            for (int mt = 0; mt < 2; mt++)
                MMA_BF16(acc[mt][ntp*2+sub], al[mt][0], al[mt][1], al[mt][2], al[mt][3], bh[sub], bh[2+sub]);
    }
}

#define CPA(dst, src) \
    asm volatile("cp.async.cg.shared.global [%0], [%1], 16;" :: "r"(dst), "l"(src))

#define ISSUE_STAGE(s, b) {                                                       \
    unsigned d_ = smb + (unsigned)(b)*STG_B + (unsigned)(lr*48 + half*16);        \
    CPA(d_,         aH + (size_t)(s)*8);                                          \
    CPA(d_ + 6144u, aL + (size_t)(s)*8);                                          \
    if (t < 128) {                                                                \
        unsigned e_ = smb + (unsigned)(b)*STG_B + 12288u + (unsigned)(lr*48 + half*16); \
        CPA(e_,         bH + (size_t)(s)*8);                                      \
        CPA(e_ + 3072u, bL + (size_t)(s)*8);                                      \
    }                                                                             \
    asm volatile("cp.async.commit_group;" ::: "memory"); }

#define GEMM_LOOP(NS_) {                                                          \
    ISSUE_STAGE(0, 0);                                                            \
    ISSUE_STAGE(1, 1);                                                            \
    ISSUE_STAGE(2, 2);                                                            \
    for (int i = 0; i < (NS_); i++) {                                             \
        const int rem = (NS_) - 1 - i;                                            \
        if (rem >= 2)      { asm volatile("cp.async.wait_group 2;" ::: "memory"); }\
        else if (rem == 1) { asm volatile("cp.async.wait_group 1;" ::: "memory"); }\
        else               { asm volatile("cp.async.wait_group 0;" ::: "memory"); }\
        __syncthreads();                                                          \
        const unsigned bb = smb + (unsigned)(i & 3) * STG_B;                      \
        compute_stage(bb, bb + 6144u, bb + 12288u, bb + 15360u, wm, wn, lane, acc);\
        if (i + 3 < (NS_)) ISSUE_STAGE(i + 3, (i + 3) & 3);                       \
    } }

#define ISSUE_PV(s, b) {                                                          \
    unsigned d_ = smb + (unsigned)(b)*STG_PV + (unsigned)(lr*48 + half*16);       \
    CPA(d_,         aH + (size_t)(s)*8);                                          \
    CPA(d_ + 6144u, aL + (size_t)(s)*8);                                          \
    if (t < 128) {                                                                \
        unsigned e_ = smb + (unsigned)(b)*STG_PV + 12288u                         \
                    + (unsigned)((t>>3)*BPITCH + (t&7)*16);                       \
        CPA(e_,         vbh + (size_t)(s)*16*128);                                \
        CPA(e_ + 2304u, vbl + (size_t)(s)*16*128);                                \
    }                                                                             \
    asm volatile("cp.async.commit_group;" ::: "memory"); }

#define GEMM_LOOP_PV(NS_) {                                                       \
    ISSUE_PV(0, 0);                                                               \
    ISSUE_PV(1, 1);                                                               \
    ISSUE_PV(2, 2);                                                               \
    for (int i = 0; i < (NS_); i++) {                                             \
        const int rem = (NS_) - 1 - i;                                            \
        if (rem >= 2)      { asm volatile("cp.async.wait_group 2;" ::: "memory"); }\
        else if (rem == 1) { asm volatile("cp.async.wait_group 1;" ::: "memory"); }\
        else               { asm volatile("cp.async.wait_group 0;" ::: "memory"); }\
        __syncthreads();                                                          \
        const unsigned bb = smb + (unsigned)(i & 3) * STG_PV;                     \
        compute_stage_pv(bb, bb + 6144u, bb + 12288u, bb + 14592u, wm, wn, lane, acc);\
        if (i + 3 < (NS_)) ISSUE_PV(i + 3, (i + 3) & 3);                          \
    } }

// ---------------------------------------------------------------------------
// Kernel 0: pre-split all three fp32 operands -> hi/lo packed bf16 (one launch)
// ---------------------------------------------------------------------------
#define NXW  (TOK*ED/2)
#define NWAW (QKV*ED/2)
#define NWOW (ED*NE/2)
__global__ void __launch_bounds__(256) split_all(const float* __restrict__ x,
                                                 const float* __restrict__ wa,
                                                 const float* __restrict__ wo) {
    int i = blockIdx.x * 256 + threadIdx.x;
    const float* src; unsigned *H, *L; int j = i;
    if (j < NXW)              { src = x;  H = g_xh;  L = g_xl; }
    else if ((j -= NXW) < NWAW) { src = wa; H = g_wah; L = g_wal; }
    else if ((j -= NWAW) < NWOW){ src = wo; H = g_woh; L = g_wol; }
    else return;
    float2 v = ((const float2*)src)[j];
    unsigned h, l;
    split2(v.x, v.y, h, l);
    H[j] = h; L[j] = l;
}

// Q/K/V epilogue writer: raw-view remap baked in. row = global token, col in [0,2048)
__device__ __forceinline__ void write_qk(unsigned* H, unsigned* L, int row, int col,
                                         float v0, float v1) {
    int b = row >> 10, sp = row & 1023;
    int h = sp >> 7, s = ((sp & 127) << 3) + (col >> 8), d = col & 255;
    size_t idx = ((((size_t)(b*8 + h)) * SQL + s) << 7) + (d >> 1);
    unsigned hh, ll;
    split2(v0, v1, hh, ll);
    H[idx] = hh; L[idx] = ll;
}

// ---------------------------------------------------------------------------
// Kernel 1: proj = x @ w_attn^T + b_attn; m-half selected by mbase (tiles)
// ---------------------------------------------------------------------------
__global__ void __launch_bounds__(256, 3) proj_gemm(const float* __restrict__ bias,
                                                    int mbase) {
    extern __shared__ unsigned smd[];
    const unsigned smb = smem_u32(smd);
    const int m0 = (mbase + blockIdx.y) * BM, n0 = blockIdx.x * BN;
    const int t = threadIdx.x, lane = t & 31, w = t >> 5;
    const int wm = w >> 1, wn = w & 1;
    const int lr = t >> 1, half = t & 1;
    const unsigned* aH = g_xh  + (size_t)(m0 + lr) * 128 + half*4;
    const unsigned* aL = g_xl  + (size_t)(m0 + lr) * 128 + half*4;
    const unsigned* bH = g_wah + (size_t)(n0 + lr) * 128 + half*4;
    const unsigned* bL = g_wal + (size_t)(n0 + lr) * 128 + half*4;
    float acc[2][4][4] = {};
    GEMM_LOOP(ED/BK);

    const int g = lane >> 2, qq = lane & 3;
    #pragma unroll
    for (int mt = 0; mt < 2; mt++) {
        int row = m0 + wm*32 + mt*16 + g;
        #pragma unroll
        for (int nt = 0; nt < 4; nt++) {
            int col = n0 + wn*32 + nt*8 + qq*2;
            float bv0 = bias[col], bv1 = bias[col+1];
            float p0 = acc[mt][nt][0] + bv0, p1 = acc[mt][nt][1] + bv1;
            float p2 = acc[mt][nt][2] + bv0, p3 = acc[mt][nt][3] + bv1;
            unsigned *H, *L; int c;
            if (col < NE)          { H = g_qh; L = g_ql; c = col; }
            else if (col < 2*NE)   { H = g_kh; L = g_kl; c = col - NE; }
            else                   { H = g_vh; L = g_vl; c = col - 2*NE; }
            write_qk(H, L, row,   c, p0, p1);
            write_qk(H, L, row+8, c, p2, p3);
        }
    }
}

// ---------------------------------------------------------------------------
// Kernel 2: scores = (Q·K^T)/16; bh-half via zbase; skip masked tiles
// ---------------------------------------------------------------------------
__global__ void __launch_bounds__(256, 3) score_gemm(int zbase) {
    const int q0 = blockIdx.y * BM, k0 = blockIdx.x * BN;
    if (k0 > q0 + (BM - 1)) return;
    const int bh = zbase + blockIdx.z;
    extern __shared__ unsigned smd[];
    const unsigned smb = smem_u32(smd);
    const int t = threadIdx.x, lane = t & 31, w = t >> 5;
    const int wm = w >> 1, wn = w & 1;
    const int lr = t >> 1, half = t & 1;
    const unsigned* aH = g_qh + ((size_t)bh * SQL + q0 + lr) * 128 + half*4;
    const unsigned* aL = g_ql + ((size_t)bh * SQL + q0 + lr) * 128 + half*4;
    const unsigned* bH = g_kh + ((size_t)bh * SQL + k0 + lr) * 128 + half*4;
    const unsigned* bL = g_kl + ((size_t)bh * SQL + k0 + lr) * 128 + half*4;
    float acc[2][4][4] = {};
    GEMM_LOOP(ED/BK);

    float* S = g_scores + (size_t)bh * SQL * SQL;
    const int g = lane >> 2, qq = lane & 3;
    #pragma unroll
    for (int mt = 0; mt < 2; mt++) {
        int row = q0 + wm*32 + mt*16 + g;
        #pragma unroll
        for (int nt = 0; nt < 4; nt++) {
            int col = k0 + wn*32 + nt*8 + qq*2;
            float* d0 = S + (size_t)row * SQL + col;
            float* d1 = S + (size_t)(row+8) * SQL + col;
            *(float2*)d0 = make_float2(acc[mt][nt][0]*0.0625f, acc[mt][nt][1]*0.0625f);
            *(float2*)d1 = make_float2(acc[mt][nt][2]*0.0625f, acc[mt][nt][3]*0.0625f);
        }
    }
}

// ---------------------------------------------------------------------------
// Kernel 3: causal softmax (cols < kend only); row-half via rbase
// ---------------------------------------------------------------------------
__global__ void __launch_bounds__(128) softmax_rows(int rbase) {
    const int row = rbase + blockIdx.x;
    const int q = row & (SQL - 1);
    const int kend = ((q >> 7) + 1) << 7;
    const float* r = g_scores + (size_t)row * SQL;
    const int t = threadIdx.x;
    const int k0 = t * 8;
    const bool act = (k0 < kend);
    float v[8];
    float mx = -1e30f;
    if (act) {
        float4 x0 = *(const float4*)(r + k0);
        float4 x1 = *(const float4*)(r + k0 + 4);
        v[0]=x0.x; v[1]=x0.y; v[2]=x0.z; v[3]=x0.w;
        v[4]=x1.x; v[5]=x1.y; v[6]=x1.z; v[7]=x1.w;
        #pragma unroll
        for (int i = 0; i < 8; i++) {
            v[i] = (k0 + i <= q) ? v[i] : -1e30f;
            mx = fmaxf(mx, v[i]);
        }
    }
    __shared__ float redm[4], reds[4];
    #pragma unroll
    for (int o = 16; o > 0; o >>= 1) mx = fmaxf(mx, __shfl_xor_sync(0xffffffffu, mx, o));
    if ((t & 31) == 0) redm[t >> 5] = mx;
    __syncthreads();
    mx = fmaxf(fmaxf(redm[0], redm[1]), fmaxf(redm[2], redm[3]));
    float sum = 0.f;
    if (act) {
        #pragma unroll
        for (int i = 0; i < 8; i++) {
            v[i] = (k0 + i <= q) ? __expf(v[i] - mx) : 0.f;
            sum += v[i];
        }
    }
    #pragma unroll
    for (int o = 16; o > 0; o >>= 1) sum += __shfl_xor_sync(0xffffffffu, sum, o);
    if ((t & 31) == 0) reds[t >> 5] = sum;
    __syncthreads();
    sum = reds[0] + reds[1] + reds[2] + reds[3];
    if (act) {
        float inv = 1.f / sum;
        unsigned hh[4], ll[4];
        #pragma unroll
        for (int j = 0; j < 4; j++)
            split2(v[2*j] * inv, v[2*j+1] * inv, hh[j], ll[j]);
        *(uint4*)(g_ph + (size_t)row * 512 + t*4) = make_uint4(hh[0], hh[1], hh[2], hh[3]);
        *(uint4*)(g_pl + (size_t)row * 512 + t*4) = make_uint4(ll[0], ll[1], ll[2], ll[3]);
    }
}

// ---------------------------------------------------------------------------
// Kernel 4: O = P @ V (ldsm.trans B frags); bh-half via zbase; causal trunc
// ---------------------------------------------------------------------------
__global__ void __launch_bounds__(256, 3) pv_gemm(int zbase) {
    const int bh = zbase + blockIdx.z;
    const int q0 = (int)(gridDim.y - 1 - blockIdx.y) * BM;   // heavy tiles first
    const int n0 = blockIdx.x * BN;
    extern __shared__ unsigned smd[];
    const unsigned smb = smem_u32(smd);
    const int t = threadIdx.x, lane = t & 31, w = t >> 5;
    const int wm = w >> 1, wn = w & 1;
    const int lr = t >> 1, half = t & 1;
    const int NS = (q0 + BM) / BK;
    const unsigned* aH = g_ph + ((size_t)bh * SQL + q0 + lr) * 512 + half*4;
    const unsigned* aL = g_pl + ((size_t)bh * SQL + q0 + lr) * 512 + half*4;
    const unsigned* vbh = g_vh + ((size_t)bh * SQL + (t>>3)) * 128 + (n0>>1) + (t&7)*4;
    const unsigned* vbl = g_vl + ((size_t)bh * SQL + (t>>3)) * 128 + (n0>>1) + (t&7)*4;
    float acc[2][4][4] = {};
    GEMM_LOOP_PV(NS);

    const int g = lane >> 2, qq = lane & 3;
    #pragma unroll
    for (int mt = 0; mt < 2; mt++) {
        int row = q0 + wm*32 + mt*16 + g;
        #pragma unroll
        for (int nt = 0; nt < 4; nt++) {
            int col = n0 + wn*32 + nt*8 + qq*2;
            size_t i0 = ((size_t)bh * SQL + row) * 128 + (col >> 1);
            size_t i1 = ((size_t)bh * SQL + row + 8) * 128 + (col >> 1);
            unsigned hh, ll;
            split2(acc[mt][nt][0], acc[mt][nt][1], hh, ll);
            g_ah[i0] = hh; g_al[i0] = ll;
            split2(acc[mt][nt][2], acc[mt][nt][3], hh, ll);
            g_ah[i1] = hh; g_al[i1] = ll;
        }
    }
}

// ---------------------------------------------------------------------------
// Kernel 5: out partials (split-K=3): z in {0,1,2}, k-chunks 43/43/42 stages
// ---------------------------------------------------------------------------
__global__ void __launch_bounds__(256, 3) out_gemm() {
    extern __shared__ unsigned smd[];
    const unsigned smb = smem_u32(smd);
    const int m0 = blockIdx.y * BM, n0 = blockIdx.x * BN;
    const int z = blockIdx.z;
    float* P = (z == 0) ? g_op0 : (z == 1) ? g_op1 : g_op2;
    const int kw0 = z * 43 * 8;
    const int NSz = (z == 2) ? 42 : 43;
    const int t = threadIdx.x, lane = t & 31, w = t >> 5;
    const int wm = w >> 1, wn = w & 1;
    const int lr = t >> 1, half = t & 1;
    const unsigned* aH = g_ah  + (size_t)(m0 + lr) * 1024 + kw0 + half*4;
    const unsigned* aL = g_al  + (size_t)(m0 + lr) * 1024 + kw0 + half*4;
    const unsigned* bH = g_woh + (size_t)(n0 + lr) * 1024 + kw0 + half*4;
    const unsigned* bL = g_wol + (size_t)(n0 + lr) * 1024 + kw0 + half*4;
    float acc[2][4][4] = {};
    GEMM_LOOP(NSz);

    const int g = lane >> 2, qq = lane & 3;
    #pragma unroll
    for (int mt = 0; mt < 2; mt++) {
        int row = m0 + wm*32 + mt*16 + g;
        #pragma unroll
        for (int nt = 0; nt < 4; nt++) {
            int col = n0 + wn*32 + nt*8 + qq*2;
            *(float2*)(P + (size_t)row * ED + col) =
                make_float2(acc[mt][nt][0], acc[mt][nt][1]);
            *(float2*)(P + (size_t)(row+8) * ED + col) =
                make_float2(acc[mt][nt][2], acc[mt][nt][3]);
        }
    }
}

// Kernel 6: C = op0 + op1 + op2 + bias
__global__ void __launch_bounds__(256) out_reduce(const float* __restrict__ bias,
                                                  float* __restrict__ C) {
    int i = blockIdx.x * 256 + threadIdx.x;
    float4 a = ((const float4*)g_op0)[i];
    float4 b = ((const float4*)g_op1)[i];
    float4 c = ((const float4*)g_op2)[i];
    int col = (i * 4) & (ED - 1);
    float4 bb = *(const float4*)(bias + col);
    ((float4*)C)[i] = make_float4(a.x+b.x+c.x+bb.x, a.y+b.y+c.y+bb.y,
                                  a.z+b.z+c.z+bb.z, a.w+b.w+c.w+bb.w);
}

extern "C" void kernel_launch(void* const* d_in, const int* in_sizes, int n_in,
                              void* d_out, int out_size) {
    const float* x      = (const float*)d_in[0];
    const float* w_attn = (const float*)d_in[1];
    const float* b_attn = (const float*)d_in[2];
    const float* w_out  = (const float*)d_in[3];
    const float* b_out  = (const float*)d_in[4];
    float* out = (float*)d_out;

    cudaFuncSetAttribute(proj_gemm,  cudaFuncAttributeMaxDynamicSharedMemorySize, SMEM_SZ);
    cudaFuncSetAttribute(score_gemm, cudaFuncAttributeMaxDynamicSharedMemorySize, SMEM_SZ);
    cudaFuncSetAttribute(pv_gemm,    cudaFuncAttributeMaxDynamicSharedMemorySize, NPIPE*STG_PV);
    cudaFuncSetAttribute(out_gemm,   cudaFuncAttributeMaxDynamicSharedMemorySize, SMEM_SZ);

    // Fork/join: two independent bh-half pipelines (batches 0-1 vs 2-3).
    // Streams/events are created AND destroyed within this call so device
    // memory returns to the harness baseline (allocation guard).
    cudaStream_t s1, s2;
    cudaStreamCreateWithFlags(&s1, cudaStreamNonBlocking);
    cudaStreamCreateWithFlags(&s2, cudaStreamNonBlocking);
    cudaEvent_t eF, e1, e2;
    cudaEventCreateWithFlags(&eF, cudaEventDisableTiming);
    cudaEventCreateWithFlags(&e1, cudaEventDisableTiming);
    cudaEventCreateWithFlags(&e2, cudaEventDisableTiming);

    const int NTOT = NXW + NWAW + NWOW;
    split_all<<<(NTOT + 255)/256, 256>>>(x, w_attn, w_out);
    cudaEventRecord(eF, 0);
    cudaStreamWaitEvent(s1, eF, 0);
    cudaStreamWaitEvent(s2, eF, 0);

    // half 0: batches 0-1 (proj m-tiles 0..15, bh 0..15)
    proj_gemm<<<dim3(QKV/BN, TOK/BM/2), 256, SMEM_SZ, s1>>>(b_attn, 0);
    score_gemm<<<dim3(SQL/BN, SQL/BM, NBH/2), 256, SMEM_SZ, s1>>>(0);
    softmax_rows<<<NBH*SQL/2, 128, 0, s1>>>(0);
    pv_gemm<<<dim3(ED/BN, SQL/BM, NBH/2), 256, NPIPE*STG_PV, s1>>>(0);

    // half 1: batches 2-3 (proj m-tiles 16..31, bh 16..31)
    proj_gemm<<<dim3(QKV/BN, TOK/BM/2), 256, SMEM_SZ, s2>>>(b_attn, TOK/BM/2);
    score_gemm<<<dim3(SQL/BN, SQL/BM, NBH/2), 256, SMEM_SZ, s2>>>(NBH/2);
    softmax_rows<<<NBH*SQL/2, 128, 0, s2>>>(NBH*SQL/2);
    pv_gemm<<<dim3(ED/BN, SQL/BM, NBH/2), 256, NPIPE*STG_PV, s2>>>(NBH/2);

    cudaEventRecord(e1, s1);
    cudaEventRecord(e2, s2);
    cudaStreamWaitEvent(0, e1, 0);
    cudaStreamWaitEvent(0, e2, 0);

    out_gemm<<<dim3(ED/BN, TOK/BM, 3), 256, SMEM_SZ>>>();
    out_reduce<<<TOK*ED/4/256, 256>>>(b_out, out);

    // Release driver-side resources (side streams are fully joined above;
    // captured nodes live in the graph, not in the stream objects).
    cudaEventDestroy(eF);
    cudaEventDestroy(e1);
    cudaEventDestroy(e2);
    cudaStreamDestroy(s1);
    cudaStreamDestroy(s2);
}